// round 5
// baseline (speedup 1.0000x reference)
#include <cuda_runtime.h>
#include <cstdint>

#define Bn 64
#define Tn 188
#define In 512
#define Hn 1024
#define G4 (4*Hn)
#define G6 (6*Hn)

// ---------------- persistent device scratch (allocation-free rule) ----------
__device__ float g_prex[(size_t)Tn * Bn * G4];     // [t][b][4H]
__device__ float g_P[2][(size_t)Bn * G6];          // split-K partials, [b][6144]
__device__ float g_h[2][Bn * Hn];                  // ping-pong hidden (fp32)
__device__ float g_c[2][Bn * Hn];                  // ping-pong cell (fp32)
__device__ float g_ht[2][Bn * Hn];                 // tf32-rounded hidden (GEMM B)
__device__ float g_ct[2][Bn * Hn];                 // tf32-rounded cell (GEMM B)
__device__ float g_W[(size_t)G6 * Hn];             // [whh;wrec] tf32-rounded
__device__ float g_Wih[(size_t)G4 * In];           // wih tf32-rounded
__device__ float g_X[(size_t)Bn * Tn * In];        // x tf32-rounded

__device__ __forceinline__ float sigf(float x){ return 1.f / (1.f + __expf(-x)); }

__device__ __forceinline__ float tf32r(float x){
    uint32_t u; asm("cvt.rna.tf32.f32 %0, %1;" : "=r"(u) : "f"(x));
    return __uint_as_float(u);
}

#define CPA16(dst, src) \
    asm volatile("cp.async.cg.shared.global [%0], [%1], 16;" :: "r"(dst), "l"(src) : "memory")
#define CPC()  asm volatile("cp.async.commit_group;" ::: "memory")
#define CPW(n) asm volatile("cp.async.wait_group %0;" :: "n"(n) : "memory")

// ---------------- smem layout (float offsets) -------------------------------
// A tiles: [128][36], B tiles: [64][36], double buffered. 36-float k-stride
// makes all mma fragment loads bank-conflict-free.
#define OA0 0
#define OA1 4608
#define OB0 9216
#define OB1 11520
#define SMEM_BYTES (13824 * 4)

#define KC 32
#define NCH 16   // both GEMMs see K-extent 512 per CTA (step uses split-K=2)

__device__ __forceinline__ void ldtile(float* s, const float* __restrict__ g,
                                       int ldK, int k0, int tid, int rows){
    const int units = rows * 8;                 // 16B units per chunk
    for (int u = tid; u < units; u += 128){
        int r  = u >> 3;
        int kq = (u & 7) * 4;
        uint32_t dst = (uint32_t)__cvta_generic_to_shared(s + r * 36 + kq);
        CPA16(dst, g + (size_t)r * ldK + k0 + kq);
    }
}

// ---------------------------------------------------------------------------
// mma.sync tf32 GEMM: D[128,64] = A[128,512] * B[64,512]^T (K-major both).
// MODE 0 (step): grid (48,2). m tiles 0..31 -> Whh x h, 32..47 -> Wrec x c.
//                blockIdx.y = K-split. Output -> g_P[split][b][6144].
// MODE 1 (prex): grid (32,188). A = Wih, B = x rows (b,t). Output -> g_prex+bias.
// ---------------------------------------------------------------------------
template<int MODE>
__global__ void __launch_bounds__(128)
gemm_mma(const float* __restrict__ bias, int par)
{
    extern __shared__ float sm[];
    const int tid  = threadIdx.x;
    const int wid  = tid >> 5;
    const int lane = tid & 31;
    const int lr   = lane >> 2;
    const int lc   = lane & 3;
    const int m    = blockIdx.x;
    const int sp   = blockIdx.y;

    const float* A; const float* B; int ldA, ldB;
    if (MODE == 0){
        A   = g_W + (size_t)m * 128 * Hn + sp * 512;
        ldA = Hn;
        B   = ((m < 32) ? g_ht[par] : g_ct[par]) + sp * 512;
        ldB = Hn;
    } else {
        A   = g_Wih + (size_t)m * 128 * In;
        ldA = In;
        B   = g_X + (size_t)sp * 64 * In;
        ldB = In;
    }

    float acc[2][8][4];
#pragma unroll
    for (int f = 0; f < 2; f++)
#pragma unroll
        for (int j = 0; j < 8; j++)
#pragma unroll
            for (int q = 0; q < 4; q++) acc[f][j][q] = 0.f;

    ldtile(sm + OA0, A, ldA, 0, tid, 128);
    ldtile(sm + OB0, B, ldB, 0, tid, 64);
    CPC();

#pragma unroll 1
    for (int ch = 0; ch < NCH; ch++){
        if (ch + 1 < NCH){
            int bo = (ch + 1) & 1;
            ldtile(sm + (bo ? OA1 : OA0), A, ldA, (ch + 1) * KC, tid, 128);
            ldtile(sm + (bo ? OB1 : OB0), B, ldB, (ch + 1) * KC, tid, 64);
            CPC();
            CPW(1);
        } else {
            CPW(0);
        }
        __syncthreads();

        const uint32_t* As = (const uint32_t*)(sm + ((ch & 1) ? OA1 : OA0));
        const uint32_t* Bs = (const uint32_t*)(sm + ((ch & 1) ? OB1 : OB0));

#pragma unroll
        for (int kk = 0; kk < 4; kk++){
            const int kb = kk * 8 + lc;
            uint32_t a[2][4], b[8][2];
#pragma unroll
            for (int fm = 0; fm < 2; fm++){
                int base = (wid * 32 + fm * 16 + lr) * 36 + kb;
                a[fm][0] = As[base];
                a[fm][1] = As[base + 8 * 36];
                a[fm][2] = As[base + 4];
                a[fm][3] = As[base + 8 * 36 + 4];
            }
#pragma unroll
            for (int j = 0; j < 8; j++){
                int bb = (j * 8 + lr) * 36 + kb;
                b[j][0] = Bs[bb];
                b[j][1] = Bs[bb + 4];
            }
#pragma unroll
            for (int fm = 0; fm < 2; fm++)
#pragma unroll
                for (int j = 0; j < 8; j++)
                    asm volatile(
                        "mma.sync.aligned.m16n8k8.row.col.f32.tf32.tf32.f32 "
                        "{%0,%1,%2,%3}, {%4,%5,%6,%7}, {%8,%9}, {%0,%1,%2,%3};"
                        : "+f"(acc[fm][j][0]), "+f"(acc[fm][j][1]),
                          "+f"(acc[fm][j][2]), "+f"(acc[fm][j][3])
                        : "r"(a[fm][0]), "r"(a[fm][1]), "r"(a[fm][2]), "r"(a[fm][3]),
                          "r"(b[j][0]), "r"(b[j][1]));
        }
        __syncthreads();
    }

    // ---------------- epilogue ----------------
    const int rowbase = m * 128 + wid * 32;
    if (MODE == 0){
        float* __restrict__ P = g_P[sp];
#pragma unroll
        for (int fm = 0; fm < 2; fm++)
#pragma unroll
            for (int j = 0; j < 8; j++)
#pragma unroll
                for (int q = 0; q < 4; q++){
                    int row = rowbase + fm * 16 + lr + (q >> 1) * 8;
                    int col = j * 8 + lc * 2 + (q & 1);
                    P[(size_t)col * G6 + row] = acc[fm][j][q];
                }
    } else {
        float bs[2][2];
#pragma unroll
        for (int fm = 0; fm < 2; fm++){
            bs[fm][0] = bias[rowbase + fm * 16 + lr];
            bs[fm][1] = bias[rowbase + fm * 16 + lr + 8];
        }
        const int n0 = sp * 64;
#pragma unroll
        for (int fm = 0; fm < 2; fm++)
#pragma unroll
            for (int j = 0; j < 8; j++)
#pragma unroll
                for (int q = 0; q < 4; q++){
                    int row = rowbase + fm * 16 + lr + (q >> 1) * 8;
                    int n   = n0 + j * 8 + lc * 2 + (q & 1);
                    int bq  = n / Tn;
                    int tq  = n - bq * Tn;
                    g_prex[((size_t)tq * Bn + bq) * G4 + row] =
                        acc[fm][j][q] + bs[fm][q >> 1];
                }
    }
}

// ---------------------------------------------------------------------------
__global__ void cvt_all(const float* __restrict__ whh, const float* __restrict__ wrec,
                        const float* __restrict__ wih, const float* __restrict__ x)
{
    const size_t n0 = (size_t)4096 * 1024;
    const size_t n1 = (size_t)2048 * 1024;
    const size_t n2 = (size_t)4096 * 512;
    const size_t n3 = (size_t)Bn * Tn * In;
    const size_t NT = n0 + n1 + n2 + n3;
    for (size_t i = (size_t)blockIdx.x * blockDim.x + threadIdx.x; i < NT;
         i += (size_t)gridDim.x * blockDim.x){
        if (i < n0)                g_W[i]                 = tf32r(whh[i]);
        else if (i < n0 + n1)      g_W[i]                 = tf32r(wrec[i - n0]);
        else if (i < n0 + n1 + n2) g_Wih[i - n0 - n1]     = tf32r(wih[i - n0 - n1]);
        else                       g_X[i - n0 - n1 - n2]  = tf32r(x[i - n0 - n1 - n2]);
    }
}

__global__ void init_state(const float* __restrict__ h0, const float* __restrict__ c0){
    int i = blockIdx.x * blockDim.x + threadIdx.x;
    if (i < Bn * Hn){
        float h = h0[i], c = c0[i];
        g_h[0][i] = h;  g_c[0][i] = c;
        g_ht[0][i] = tf32r(h);  g_ct[0][i] = tf32r(c);
    }
}

__global__ void __launch_bounds__(256)
cell_kernel(const int* __restrict__ lengths, float* __restrict__ out,
            int t, int par, int writeC)
{
    int idx = blockIdx.x * 256 + threadIdx.x;    // 0..65535
    int j = idx & (Hn - 1);
    int b = idx >> 10;

    const float* __restrict__ P0 = g_P[0] + (size_t)b * G6;
    const float* __restrict__ P1 = g_P[1] + (size_t)b * G6;
    size_t pxb = ((size_t)t * Bn + b) * G4 + j;

    float pi = g_prex[pxb]          + P0[j]          + P1[j]
             + P0[4 * Hn + j] + P1[4 * Hn + j];
    float pf = g_prex[pxb + Hn]     + P0[Hn + j]     + P1[Hn + j]
             + P0[5 * Hn + j] + P1[5 * Hn + j];
    float pg = g_prex[pxb + 2 * Hn] + P0[2 * Hn + j] + P1[2 * Hn + j];
    float po = g_prex[pxb + 3 * Hn] + P0[3 * Hn + j] + P1[3 * Hn + j];
    float cold = g_c[par][b * Hn + j];

    float ig = sigf(pi);
    float fg = sigf(pf);
    float gv = tanhf(pg);
    float cn = fg * cold + ig * gv;
    float og = sigf(po + cn);
    float hn = og * tanhf(cn);
    float mval = (t < lengths[b]) ? 1.f : 0.f;
    hn *= mval; cn *= mval;

    int np = par ^ 1;
    g_h[np][b * Hn + j]  = hn;
    g_c[np][b * Hn + j]  = cn;
    g_ht[np][b * Hn + j] = tf32r(hn);
    g_ct[np][b * Hn + j] = tf32r(cn);

    size_t ob = ((size_t)b * Tn + t) * Hn + j;
    out[ob] = hn;
    if (writeC) out[(size_t)Bn * Tn * Hn + ob] = cn;
}

// ---------------------------------------------------------------------------
extern "C" void kernel_launch(void* const* d_in, const int* in_sizes, int n_in,
                              void* d_out, int out_size)
{
    const float* x    = (const float*)d_in[0];
    const float* h0   = (const float*)d_in[1];
    const float* c0   = (const float*)d_in[2];
    const float* wih  = (const float*)d_in[3];
    const float* whh  = (const float*)d_in[4];
    const float* wrec = (const float*)d_in[5];
    const float* bias = (const float*)d_in[6];
    const int* lengths = (const int*)d_in[7];
    float* out = (float*)d_out;
    int writeC = (out_size >= 2 * Bn * Tn * Hn) ? 1 : 0;

    cudaFuncSetAttribute(gemm_mma<0>, cudaFuncAttributeMaxDynamicSharedMemorySize, SMEM_BYTES);
    cudaFuncSetAttribute(gemm_mma<1>, cudaFuncAttributeMaxDynamicSharedMemorySize, SMEM_BYTES);

    cvt_all<<<4096, 256>>>(whh, wrec, wih, x);
    init_state<<<256, 256>>>(h0, c0);
    gemm_mma<1><<<dim3(32, 188), 128, SMEM_BYTES>>>(bias, 0);
    for (int t = 0; t < Tn; t++){
        gemm_mma<0><<<dim3(48, 2), 128, SMEM_BYTES>>>(nullptr, t & 1);
        cell_kernel<<<256, 256>>>(lengths, out, t, t & 1, writeC);
    }
}

// round 6
// speedup vs baseline: 1.1089x; 1.1089x over previous
#include <cuda_runtime.h>
#include <cstdint>

#define Bn 64
#define Tn 188
#define In 512
#define Hn 1024
#define G4 (4*Hn)
#define NCTA 144
#define NTHR 256

// ---------------- persistent device scratch (allocation-free rule) ----------
__device__ float g_prex[(size_t)Tn * Bn * G4];      // [t][b][4H]
__device__ float g_P[(size_t)3 * Bn * 6144];        // [sp][b(col)][row 6144]
__device__ float g_c[2][Bn * Hn];                   // fp32 cell state ping-pong
__device__ float g_ht[2][Bn * Hn];                  // tf32-rounded hidden
__device__ float g_ct[2][Bn * Hn];                  // tf32-rounded cell
__device__ float g_Wpk[(size_t)NCTA * 49152];       // packed W fragments per CTA
__device__ float g_Wih[(size_t)G4 * In];            // wih tf32-rounded
__device__ float g_X[(size_t)Bn * Tn * In];         // x tf32-rounded
__device__ unsigned g_bar_ct = 0;
__device__ unsigned g_bar_ep = 0;

__device__ __forceinline__ float sigf(float x){ return 1.f / (1.f + __expf(-x)); }
__device__ __forceinline__ float tf32r(float x){
    uint32_t u; asm("cvt.rna.tf32.f32 %0, %1;" : "=r"(u) : "f"(x));
    return __uint_as_float(u);
}

#define CPA16(dst, src) \
    asm volatile("cp.async.cg.shared.global [%0], [%1], 16;" :: "r"(dst), "l"(src) : "memory")
#define CPC()  asm volatile("cp.async.commit_group;" ::: "memory")
#define CPW(n) asm volatile("cp.async.wait_group %0;" :: "n"(n) : "memory")

#define MMA_TF32(acc, a0,a1,a2,a3, b0,b1) \
    asm volatile("mma.sync.aligned.m16n8k8.row.col.f32.tf32.tf32.f32 " \
        "{%0,%1,%2,%3}, {%4,%5,%6,%7}, {%8,%9}, {%0,%1,%2,%3};" \
        : "+f"((acc)[0]), "+f"((acc)[1]), "+f"((acc)[2]), "+f"((acc)[3]) \
        : "r"(a0), "r"(a1), "r"(a2), "r"(a3), "r"(b0), "r"(b1))

// ---------------------------------------------------------------------------
// Prep kernels
// ---------------------------------------------------------------------------
__device__ __forceinline__ float Wat(const float* whh, const float* wrec, int r, int c){
    return (r < 4096) ? whh[(size_t)r * Hn + c] : wrec[(size_t)(r - 4096) * Hn + c];
}

// Pack W into per-CTA fragment-major layout:
// slot = (((ck*4+kk)*4 + w)*2 + mt)*32 + lane ; float4 = {A[R0][C0],A[R0+8][C0],A[R0][C0+4],A[R0+8][C0+4]}
__global__ void pack_w(const float* __restrict__ whh, const float* __restrict__ wrec){
    const int total = NCTA * 12288;
    for (int s = blockIdx.x * blockDim.x + threadIdx.x; s < total;
         s += gridDim.x * blockDim.x){
        int cta = s / 12288, slot = s % 12288;
        int tt = cta / 3, sp = cta % 3;
        int nch = (sp == 2) ? 8 : 12;
        int lane = slot & 31; int r = slot >> 5;
        int mt = r & 1; r >>= 1;
        int w  = r & 3; r >>= 2;
        int kk = r & 3; int ck = r >> 2;
        if (ck >= nch) continue;
        int R0 = tt * 128 + w * 32 + mt * 16 + (lane >> 2);
        int C0 = sp * 384 + ck * 32 + kk * 8 + (lane & 3);
        float4 v;
        v.x = tf32r(Wat(whh, wrec, R0,     C0));
        v.y = tf32r(Wat(whh, wrec, R0 + 8, C0));
        v.z = tf32r(Wat(whh, wrec, R0,     C0 + 4));
        v.w = tf32r(Wat(whh, wrec, R0 + 8, C0 + 4));
        *(float4*)&g_Wpk[(size_t)cta * 49152 + (size_t)slot * 4] = v;
    }
}

__global__ void cvt_xw(const float* __restrict__ wih, const float* __restrict__ x){
    const size_t n2 = (size_t)G4 * In;
    const size_t n3 = (size_t)Bn * Tn * In;
    for (size_t i = (size_t)blockIdx.x * blockDim.x + threadIdx.x; i < n2 + n3;
         i += (size_t)gridDim.x * blockDim.x){
        if (i < n2) g_Wih[i] = tf32r(wih[i]);
        else        g_X[i - n2] = tf32r(x[i - n2]);
    }
}

__global__ void init_state(const float* __restrict__ h0, const float* __restrict__ c0){
    int i = blockIdx.x * blockDim.x + threadIdx.x;
    if (i < Bn * Hn){
        float h = h0[i], c = c0[i];
        g_c[0][i] = c; g_ht[0][i] = tf32r(h); g_ct[0][i] = tf32r(c);
    }
}

// ---------------------------------------------------------------------------
// Input-projection GEMM (unchanged from working R5 kernel, MODE 1 only)
// ---------------------------------------------------------------------------
#define OA0 0
#define OA1 4608
#define OB0 9216
#define OB1 11520
#define PSMEM_BYTES (13824 * 4)

__device__ __forceinline__ void ldtile(float* s, const float* __restrict__ g,
                                       int ldK, int k0, int tid, int rows, int nthr){
    const int units = rows * 8;
    for (int u = tid; u < units; u += nthr){
        int r  = u >> 3;
        int kq = (u & 7) * 4;
        uint32_t dst = (uint32_t)__cvta_generic_to_shared(s + r * 36 + kq);
        CPA16(dst, g + (size_t)r * ldK + k0 + kq);
    }
}

__global__ void __launch_bounds__(128)
gemm_prex(const float* __restrict__ bias)
{
    extern __shared__ float sm[];
    const int tid  = threadIdx.x;
    const int wid  = tid >> 5;
    const int lane = tid & 31;
    const int lr   = lane >> 2;
    const int lc   = lane & 3;
    const int m    = blockIdx.x;
    const int sp   = blockIdx.y;

    const float* A = g_Wih + (size_t)m * 128 * In;
    const float* B = g_X   + (size_t)sp * 64 * In;

    float acc[2][8][4];
#pragma unroll
    for (int f = 0; f < 2; f++)
#pragma unroll
        for (int j = 0; j < 8; j++)
#pragma unroll
            for (int q = 0; q < 4; q++) acc[f][j][q] = 0.f;

    ldtile(sm + OA0, A, In, 0, tid, 128, 128);
    ldtile(sm + OB0, B, In, 0, tid, 64, 128);
    CPC();

#pragma unroll 1
    for (int ch = 0; ch < 16; ch++){
        if (ch + 1 < 16){
            int bo = (ch + 1) & 1;
            ldtile(sm + (bo ? OA1 : OA0), A, In, (ch + 1) * 32, tid, 128, 128);
            ldtile(sm + (bo ? OB1 : OB0), B, In, (ch + 1) * 32, tid, 64, 128);
            CPC(); CPW(1);
        } else { CPW(0); }
        __syncthreads();

        const uint32_t* As = (const uint32_t*)(sm + ((ch & 1) ? OA1 : OA0));
        const uint32_t* Bs = (const uint32_t*)(sm + ((ch & 1) ? OB1 : OB0));
#pragma unroll
        for (int kk = 0; kk < 4; kk++){
            const int kb = kk * 8 + lc;
            uint32_t a[2][4], b[8][2];
#pragma unroll
            for (int fm = 0; fm < 2; fm++){
                int base = (wid * 32 + fm * 16 + lr) * 36 + kb;
                a[fm][0] = As[base];          a[fm][1] = As[base + 8 * 36];
                a[fm][2] = As[base + 4];      a[fm][3] = As[base + 8 * 36 + 4];
            }
#pragma unroll
            for (int j = 0; j < 8; j++){
                int bb = (j * 8 + lr) * 36 + kb;
                b[j][0] = Bs[bb]; b[j][1] = Bs[bb + 4];
            }
#pragma unroll
            for (int fm = 0; fm < 2; fm++)
#pragma unroll
                for (int j = 0; j < 8; j++)
                    MMA_TF32(acc[fm][j], a[fm][0], a[fm][1], a[fm][2], a[fm][3],
                             b[j][0], b[j][1]);
        }
        __syncthreads();
    }

    const int rowbase = m * 128 + wid * 32;
    float bs[2][2];
#pragma unroll
    for (int fm = 0; fm < 2; fm++){
        bs[fm][0] = bias[rowbase + fm * 16 + lr];
        bs[fm][1] = bias[rowbase + fm * 16 + lr + 8];
    }
    const int n0 = sp * 64;
#pragma unroll
    for (int fm = 0; fm < 2; fm++)
#pragma unroll
        for (int j = 0; j < 8; j++)
#pragma unroll
            for (int q = 0; q < 4; q++){
                int row = rowbase + fm * 16 + lr + (q >> 1) * 8;
                int n   = n0 + j * 8 + lc * 2 + (q & 1);
                int bq  = n / Tn, tq = n - bq * Tn;
                g_prex[((size_t)tq * Bn + bq) * G4 + row] = acc[fm][j][q] + bs[fm][q >> 1];
            }
}

// ---------------------------------------------------------------------------
// Persistent recurrent kernel
// ---------------------------------------------------------------------------
#define SW_F   49152          // W region floats
#define SB_F   2304           // one B buffer: 64*36 floats
#define PERS_SMEM ((SW_F + 2 * SB_F) * 4)

__device__ __forceinline__ void gridbar(){
    __threadfence();
    __syncthreads();
    if (threadIdx.x == 0){
        unsigned e = *(volatile unsigned*)&g_bar_ep;
        unsigned v = atomicAdd(&g_bar_ct, 1u);
        if (v == NCTA - 1){
            g_bar_ct = 0;
            __threadfence();
            atomicAdd(&g_bar_ep, 1u);
        } else {
            while (*(volatile unsigned*)&g_bar_ep == e) __nanosleep(64);
        }
    }
    __syncthreads();
    __threadfence();
}

__global__ void __launch_bounds__(NTHR, 1)
persist_kernel(const int* __restrict__ lengths, float* __restrict__ out, int writeC)
{
    extern __shared__ __align__(16) float sm[];
    float4* sW4 = (float4*)sm;
    const int tid  = threadIdx.x;
    const int wid  = tid >> 5;
    const int lane = tid & 31;
    const int lr   = lane >> 2;
    const int lc   = lane & 3;
    const int cta  = blockIdx.x;
    const int tt   = cta / 3;
    const int sp   = cta % 3;
    const int spk0 = sp * 384;
    const int nch  = (sp == 2) ? 8 : 12;

    // one-time load of packed W tile (fully coalesced)
    {
        const float4* src = (const float4*)(g_Wpk + (size_t)cta * 49152);
        int n4 = nch * 1024;
        for (int u = tid; u < n4; u += NTHR){
            uint32_t dst = (uint32_t)__cvta_generic_to_shared(sW4 + u);
            CPA16(dst, src + u);
        }
        CPC(); CPW(0);
        __syncthreads();
    }

    const size_t BTH = (size_t)Bn * Tn * Hn;

#pragma unroll 1
    for (int t = 0; t < Tn; t++){
        const int par = t & 1, np = par ^ 1;
        const float* __restrict__ Bsrc = (tt < 32) ? g_ht[par] : g_ct[par];

        float acc[2][8][4];
#pragma unroll
        for (int mt = 0; mt < 2; mt++)
#pragma unroll
            for (int j = 0; j < 8; j++)
#pragma unroll
                for (int q = 0; q < 4; q++) acc[mt][j][q] = 0.f;

        // stage chunk 0
        ldtile(sm + SW_F, Bsrc, Hn, spk0, tid, 64, NTHR);
        CPC();

#pragma unroll 1
        for (int ck = 0; ck < nch; ck++){
            CPW(0);
            __syncthreads();
            if (ck + 1 < nch){
                ldtile(sm + SW_F + ((ck + 1) & 1) * SB_F, Bsrc, Hn,
                       spk0 + (ck + 1) * 32, tid, 64, NTHR);
                CPC();
            }
            if (wid < 4){
                const uint32_t* Bs = (const uint32_t*)(sm + SW_F + (ck & 1) * SB_F);
#pragma unroll
                for (int kk = 0; kk < 4; kk++){
                    const int kb = kk * 8 + lc;
                    uint32_t b[8][2];
#pragma unroll
                    for (int j = 0; j < 8; j++){
                        int bb = (j * 8 + lr) * 36 + kb;
                        b[j][0] = Bs[bb]; b[j][1] = Bs[bb + 4];
                    }
#pragma unroll
                    for (int mt = 0; mt < 2; mt++){
                        float4 av = sW4[(((ck * 4 + kk) * 4 + wid) * 2 + mt) * 32 + lane];
                        uint32_t a0 = __float_as_uint(av.x), a1 = __float_as_uint(av.y);
                        uint32_t a2 = __float_as_uint(av.z), a3 = __float_as_uint(av.w);
#pragma unroll
                        for (int j = 0; j < 8; j++)
                            MMA_TF32(acc[mt][j], a0, a1, a2, a3, b[j][0], b[j][1]);
                    }
                }
            }
        }

        // epilogue: write partials to g_P[sp][col][row]
        if (wid < 4){
#pragma unroll
            for (int mt = 0; mt < 2; mt++)
#pragma unroll
                for (int j = 0; j < 8; j++)
#pragma unroll
                    for (int q = 0; q < 4; q++){
                        int row = tt * 128 + wid * 32 + mt * 16 + lr + (q >> 1) * 8;
                        int col = j * 8 + lc * 2 + (q & 1);
                        g_P[((size_t)(sp * 64 + col)) * 6144 + row] = acc[mt][j][q];
                    }
        }

        gridbar();

        // fused cell phase
        for (int e = cta * NTHR + tid; e < Bn * Hn; e += NCTA * NTHR){
            int j = e & (Hn - 1);
            int b = e >> 10;
            float si = 0.f, sf = 0.f, sg = 0.f, so = 0.f;
#pragma unroll
            for (int s2 = 0; s2 < 3; s2++){
                const float* Pp = g_P + ((size_t)(s2 * 64 + b)) * 6144;
                si += Pp[j]        + Pp[4096 + j];
                sf += Pp[1024 + j] + Pp[5120 + j];
                sg += Pp[2048 + j];
                so += Pp[3072 + j];
            }
            size_t pxb = ((size_t)t * Bn + b) * G4 + j;
            float pi = g_prex[pxb]           + si;
            float pf = g_prex[pxb + Hn]      + sf;
            float pg = g_prex[pxb + 2 * Hn]  + sg;
            float po = g_prex[pxb + 3 * Hn]  + so;
            float cold = g_c[par][e];

            float ig = sigf(pi);
            float fg = sigf(pf);
            float gv = tanhf(pg);
            float cn = fg * cold + ig * gv;
            float og = sigf(po + cn);
            float hn = og * tanhf(cn);
            float mv = (t < lengths[b]) ? 1.f : 0.f;
            hn *= mv; cn *= mv;

            g_c[np][e]  = cn;
            g_ht[np][e] = tf32r(hn);
            g_ct[np][e] = tf32r(cn);

            size_t ob = ((size_t)b * Tn + t) * Hn + j;
            out[ob] = hn;
            if (writeC) out[BTH + ob] = cn;
        }

        gridbar();
    }
}

// ---------------------------------------------------------------------------
extern "C" void kernel_launch(void* const* d_in, const int* in_sizes, int n_in,
                              void* d_out, int out_size)
{
    const float* x    = (const float*)d_in[0];
    const float* h0   = (const float*)d_in[1];
    const float* c0   = (const float*)d_in[2];
    const float* wih  = (const float*)d_in[3];
    const float* whh  = (const float*)d_in[4];
    const float* wrec = (const float*)d_in[5];
    const float* bias = (const float*)d_in[6];
    const int* lengths = (const int*)d_in[7];
    float* out = (float*)d_out;
    int writeC = (out_size >= 2 * Bn * Tn * Hn) ? 1 : 0;

    cudaFuncSetAttribute(gemm_prex, cudaFuncAttributeMaxDynamicSharedMemorySize, PSMEM_BYTES);
    cudaFuncSetAttribute(persist_kernel, cudaFuncAttributeMaxDynamicSharedMemorySize, PERS_SMEM);

    pack_w<<<1024, 256>>>(whh, wrec);
    cvt_xw<<<1024, 256>>>(wih, x);
    init_state<<<256, 256>>>(h0, c0);
    gemm_prex<<<dim3(32, 188), 128, PSMEM_BYTES>>>(bias);
    persist_kernel<<<NCTA, NTHR, PERS_SMEM>>>(lengths, out, writeC);
}

// round 8
// speedup vs baseline: 1.2728x; 1.1478x over previous
#include <cuda_runtime.h>
#include <cuda_fp16.h>
#include <cstdint>

#define Bn 64
#define Tn 188
#define In 512
#define Hn 1024
#define G4 (4*Hn)
#define NCTA 144
#define NTHR 256

// ---------------- persistent device scratch (allocation-free rule) ----------
__device__ float  g_prex[(size_t)Tn * Bn * G4];     // [t][b][4H]
__device__ float  g_P[(size_t)3 * Bn * 6144];       // [sp*64+col][row]
__device__ float  g_c[2][Bn * Hn];                  // fp32 cell state ping-pong
__device__ __half g_ht[2][Bn * Hn];                 // fp16 hidden (GEMM B)
__device__ __half g_ct[2][Bn * Hn];                 // fp16 cell (GEMM B)
__device__ uint4  g_Wpk[(size_t)NCTA * 6144];       // packed fp16 W fragments per CTA
__device__ float  g_Wih[(size_t)G4 * In];           // wih tf32-rounded
__device__ float  g_X[(size_t)Bn * Tn * In];        // x tf32-rounded
__device__ unsigned g_bar_ct = 0;
__device__ unsigned g_bar_ep = 0;

__device__ __forceinline__ float sigf(float x){ return 1.f / (1.f + __expf(-x)); }
__device__ __forceinline__ float tf32r(float x){
    uint32_t u; asm("cvt.rna.tf32.f32 %0, %1;" : "=r"(u) : "f"(x));
    return __uint_as_float(u);
}

#define CPA16(dst, src) \
    asm volatile("cp.async.cg.shared.global [%0], [%1], 16;" :: "r"(dst), "l"(src) : "memory")
#define CPC()  asm volatile("cp.async.commit_group;" ::: "memory")
#define CPW(n) asm volatile("cp.async.wait_group %0;" :: "n"(n) : "memory")

#define MMA_TF32(acc, a0,a1,a2,a3, b0,b1) \
    asm volatile("mma.sync.aligned.m16n8k8.row.col.f32.tf32.tf32.f32 " \
        "{%0,%1,%2,%3}, {%4,%5,%6,%7}, {%8,%9}, {%0,%1,%2,%3};" \
        : "+f"((acc)[0]), "+f"((acc)[1]), "+f"((acc)[2]), "+f"((acc)[3]) \
        : "r"(a0), "r"(a1), "r"(a2), "r"(a3), "r"(b0), "r"(b1))

#define MMA_F16(acc, a0,a1,a2,a3, b0,b1) \
    asm volatile("mma.sync.aligned.m16n8k16.row.col.f32.f16.f16.f32 " \
        "{%0,%1,%2,%3}, {%4,%5,%6,%7}, {%8,%9}, {%0,%1,%2,%3};" \
        : "+f"((acc)[0]), "+f"((acc)[1]), "+f"((acc)[2]), "+f"((acc)[3]) \
        : "r"(a0), "r"(a1), "r"(a2), "r"(a3), "r"(b0), "r"(b1))

__device__ __forceinline__ uint32_t lds32(uint32_t a){
    uint32_t v; asm volatile("ld.shared.b32 %0, [%1];" : "=r"(v) : "r"(a)); return v;
}

// ---------------------------------------------------------------------------
// Prep kernels
// ---------------------------------------------------------------------------
__device__ __forceinline__ float Wat(const float* whh, const float* wrec, int r, int c){
    return (r < 4096) ? whh[(size_t)r * Hn + c] : wrec[(size_t)(r - 4096) * Hn + c];
}
__device__ __forceinline__ uint32_t h2pk(float a, float b){
    __half2 h = __floats2half2_rn(a, b);
    return *(uint32_t*)&h;
}

// slot = (((ck*2+kk)*4 + w)*2 + mt)*32 + lane ; uint4 = fp16 A-fragment {a0,a1,a2,a3}
// a0=(R0,C0..C0+1) a1=(R0+8,C0..C0+1) a2=(R0,C0+8..9) a3=(R0+8,C0+8..9)
__global__ void pack_w(const float* __restrict__ whh, const float* __restrict__ wrec){
    const int total = NCTA * 6144;
    for (int s = blockIdx.x * blockDim.x + threadIdx.x; s < total;
         s += gridDim.x * blockDim.x){
        int cta = s / 6144, idx = s % 6144;
        int tt = cta / 3, sp = cta % 3;
        int nch = (sp == 2) ? 8 : 12;
        int lane = idx & 31; int r = idx >> 5;
        int mt = r & 1; r >>= 1;
        int w  = r & 3; r >>= 2;
        int kk = r & 1; int ck = r >> 1;
        if (ck >= nch) continue;
        int g = lane >> 2, t = lane & 3;
        int R0 = tt * 128 + w * 32 + mt * 16 + g;
        int C0 = sp * 384 + ck * 32 + kk * 16 + 2 * t;
        uint4 v;
        v.x = h2pk(Wat(whh, wrec, R0,     C0),     Wat(whh, wrec, R0,     C0 + 1));
        v.y = h2pk(Wat(whh, wrec, R0 + 8, C0),     Wat(whh, wrec, R0 + 8, C0 + 1));
        v.z = h2pk(Wat(whh, wrec, R0,     C0 + 8), Wat(whh, wrec, R0,     C0 + 9));
        v.w = h2pk(Wat(whh, wrec, R0 + 8, C0 + 8), Wat(whh, wrec, R0 + 8, C0 + 9));
        g_Wpk[(size_t)cta * 6144 + idx] = v;
    }
}

__global__ void cvt_xw(const float* __restrict__ wih, const float* __restrict__ x){
    const size_t n2 = (size_t)G4 * In;
    const size_t n3 = (size_t)Bn * Tn * In;
    for (size_t i = (size_t)blockIdx.x * blockDim.x + threadIdx.x; i < n2 + n3;
         i += (size_t)gridDim.x * blockDim.x){
        if (i < n2) g_Wih[i] = tf32r(wih[i]);
        else        g_X[i - n2] = tf32r(x[i - n2]);
    }
}

__global__ void init_state(const float* __restrict__ h0, const float* __restrict__ c0){
    int i = blockIdx.x * blockDim.x + threadIdx.x;
    if (i < Bn * Hn){
        float h = h0[i], c = c0[i];
        g_c[0][i]  = c;
        g_ht[0][i] = __float2half_rn(h);
        g_ct[0][i] = __float2half_rn(c);
    }
}

// ---------------------------------------------------------------------------
// Input-projection GEMM — UNCHANGED from passing R6 (tf32, 128 thr)
// ---------------------------------------------------------------------------
#define OA0 0
#define OA1 4608
#define OB0 9216
#define OB1 11520
#define PSMEM_BYTES (13824 * 4)

__device__ __forceinline__ void ldtile(float* s, const float* __restrict__ g,
                                       int ldK, int k0, int tid, int rows, int nthr){
    const int units = rows * 8;
    for (int u = tid; u < units; u += nthr){
        int r  = u >> 3;
        int kq = (u & 7) * 4;
        uint32_t dst = (uint32_t)__cvta_generic_to_shared(s + r * 36 + kq);
        CPA16(dst, g + (size_t)r * ldK + k0 + kq);
    }
}

__global__ void __launch_bounds__(128)
gemm_prex(const float* __restrict__ bias)
{
    extern __shared__ float sm[];
    const int tid  = threadIdx.x;
    const int wid  = tid >> 5;
    const int lane = tid & 31;
    const int lr   = lane >> 2;
    const int lc   = lane & 3;
    const int m    = blockIdx.x;
    const int sp   = blockIdx.y;

    const float* A = g_Wih + (size_t)m * 128 * In;
    const float* B = g_X   + (size_t)sp * 64 * In;

    float acc[2][8][4];
#pragma unroll
    for (int f = 0; f < 2; f++)
#pragma unroll
        for (int j = 0; j < 8; j++)
#pragma unroll
            for (int q = 0; q < 4; q++) acc[f][j][q] = 0.f;

    ldtile(sm + OA0, A, In, 0, tid, 128, 128);
    ldtile(sm + OB0, B, In, 0, tid, 64, 128);
    CPC();

#pragma unroll 1
    for (int ch = 0; ch < 16; ch++){
        if (ch + 1 < 16){
            int bo = (ch + 1) & 1;
            ldtile(sm + (bo ? OA1 : OA0), A, In, (ch + 1) * 32, tid, 128, 128);
            ldtile(sm + (bo ? OB1 : OB0), B, In, (ch + 1) * 32, tid, 64, 128);
            CPC(); CPW(1);
        } else { CPW(0); }
        __syncthreads();

        const uint32_t* As = (const uint32_t*)(sm + ((ch & 1) ? OA1 : OA0));
        const uint32_t* Bs = (const uint32_t*)(sm + ((ch & 1) ? OB1 : OB0));
#pragma unroll
        for (int kk = 0; kk < 4; kk++){
            const int kb = kk * 8 + lc;
            uint32_t a[2][4], b[8][2];
#pragma unroll
            for (int fm = 0; fm < 2; fm++){
                int base = (wid * 32 + fm * 16 + lr) * 36 + kb;
                a[fm][0] = As[base];          a[fm][1] = As[base + 8 * 36];
                a[fm][2] = As[base + 4];      a[fm][3] = As[base + 8 * 36 + 4];
            }
#pragma unroll
            for (int j = 0; j < 8; j++){
                int bb = (j * 8 + lr) * 36 + kb;
                b[j][0] = Bs[bb]; b[j][1] = Bs[bb + 4];
            }
#pragma unroll
            for (int fm = 0; fm < 2; fm++)
#pragma unroll
                for (int j = 0; j < 8; j++)
                    MMA_TF32(acc[fm][j], a[fm][0], a[fm][1], a[fm][2], a[fm][3],
                             b[j][0], b[j][1]);
        }
        __syncthreads();
    }

    const int rowbase = m * 128 + wid * 32;
    float bs[2][2];
#pragma unroll
    for (int fm = 0; fm < 2; fm++){
        bs[fm][0] = bias[rowbase + fm * 16 + lr];
        bs[fm][1] = bias[rowbase + fm * 16 + lr + 8];
    }
    const int n0 = sp * 64;
#pragma unroll
    for (int fm = 0; fm < 2; fm++)
#pragma unroll
        for (int j = 0; j < 8; j++)
#pragma unroll
            for (int q = 0; q < 4; q++){
                int row = rowbase + fm * 16 + lr + (q >> 1) * 8;
                int n   = n0 + j * 8 + lc * 2 + (q & 1);
                int bq  = n / Tn, tq = n - bq * Tn;
                g_prex[((size_t)tq * Bn + bq) * G4 + row] = acc[fm][j][q] + bs[fm][q >> 1];
            }
}

// ---------------------------------------------------------------------------
// Persistent recurrent kernel — R6 structure; only GEMM operand path -> fp16
// ---------------------------------------------------------------------------
#define SWB  98304               // packed W bytes (nch=12)
#define BBUF 5120                // one fp16 B buffer: 64 rows x 80B
#define PERS_SMEM (SWB + 2 * BBUF)

__device__ __forceinline__ void gridbar(){
    __threadfence();
    __syncthreads();
    if (threadIdx.x == 0){
        unsigned e = *(volatile unsigned*)&g_bar_ep;
        unsigned v = atomicAdd(&g_bar_ct, 1u);
        if (v == NCTA - 1){
            g_bar_ct = 0;
            __threadfence();
            atomicAdd(&g_bar_ep, 1u);
        } else {
            while (*(volatile unsigned*)&g_bar_ep == e) __nanosleep(64);
        }
    }
    __syncthreads();
    __threadfence();
}

__global__ void __launch_bounds__(NTHR, 1)
persist_kernel(const int* __restrict__ lengths, float* __restrict__ out, int writeC)
{
    extern __shared__ __align__(16) char smc[];
    const uint32_t sb = (uint32_t)__cvta_generic_to_shared(smc);
    const uint4* sW4 = (const uint4*)smc;
    const int tid  = threadIdx.x;
    const int wid  = tid >> 5;
    const int lane = tid & 31;
    const int g = lane >> 2, t = lane & 3;
    const int cta  = blockIdx.x;
    const int tt   = cta / 3;
    const int sp   = cta % 3;
    const int spk0 = sp * 384;
    const int nch  = (sp == 2) ? 8 : 12;

    // one-time coalesced load of packed fp16 W tile
    {
        const uint4* src = &g_Wpk[(size_t)cta * 6144];
        int n4 = nch * 512;
        for (int u = tid; u < n4; u += NTHR)
            CPA16(sb + u * 16, (const char*)(src + u));
        CPC(); CPW(0);
        __syncthreads();
    }

    const size_t BTH = (size_t)Bn * Tn * Hn;

#pragma unroll 1
    for (int tstep = 0; tstep < Tn; tstep++){
        const int par = tstep & 1, np = par ^ 1;
        const __half* __restrict__ Bsrc = (tt < 32) ? g_ht[par] : g_ct[par];

        float acc[2][8][4];
#pragma unroll
        for (int mt = 0; mt < 2; mt++)
#pragma unroll
            for (int j = 0; j < 8; j++)
#pragma unroll
                for (int q = 0; q < 4; q++) acc[mt][j][q] = 0.f;

        // stage fp16 B chunk: 64 rows x 32 halves (64B) into 80B-stride rows
#define ST_B16(buf, ck) do {                                                   \
        int rr = tid >> 2, uu = tid & 3;                                       \
        CPA16(sb + SWB + (buf) * BBUF + rr * 80 + uu * 16,                     \
              Bsrc + (size_t)rr * Hn + spk0 + (ck) * 32 + uu * 8);             \
    } while (0)

        ST_B16(0, 0); CPC();

#pragma unroll 1
        for (int ck = 0; ck < nch; ck++){
            CPW(0);
            __syncthreads();
            if (ck + 1 < nch){ ST_B16((ck + 1) & 1, ck + 1); CPC(); }

            if (wid < 4){
                const uint32_t Bb = sb + SWB + (ck & 1) * BBUF;
#pragma unroll
                for (int kk = 0; kk < 2; kk++){
                    uint32_t b[8][2];
#pragma unroll
                    for (int j = 0; j < 8; j++){
                        uint32_t bbase = Bb + (j * 8 + g) * 80 + kk * 32 + t * 4;
                        b[j][0] = lds32(bbase);
                        b[j][1] = lds32(bbase + 16);
                    }
#pragma unroll
                    for (int mt = 0; mt < 2; mt++){
                        uint4 av = sW4[((((ck * 2 + kk) * 4 + wid) * 2 + mt) * 32) + lane];
#pragma unroll
                        for (int j = 0; j < 8; j++)
                            MMA_F16(acc[mt][j], av.x, av.y, av.z, av.w, b[j][0], b[j][1]);
                    }
                }
            }
        }

        // epilogue: partials -> g_P[(sp*64+col)][row]  (same as R6)
        if (wid < 4){
#pragma unroll
            for (int mt = 0; mt < 2; mt++)
#pragma unroll
                for (int j = 0; j < 8; j++)
#pragma unroll
                    for (int q = 0; q < 4; q++){
                        int row = tt * 128 + wid * 32 + mt * 16 + g + (q >> 1) * 8;
                        int col = j * 8 + t * 2 + (q & 1);
                        g_P[((size_t)(sp * 64 + col)) * 6144 + row] = acc[mt][j][q];
                    }
        }

        gridbar();

        // fused cell phase (R6, plus fp16 state stores)
        for (int e = cta * NTHR + tid; e < Bn * Hn; e += NCTA * NTHR){
            int j = e & (Hn - 1);
            int b = e >> 10;
            float si = 0.f, sf = 0.f, sg = 0.f, so = 0.f;
#pragma unroll
            for (int s2 = 0; s2 < 3; s2++){
                const float* Pp = g_P + ((size_t)(s2 * 64 + b)) * 6144;
                si += Pp[j]        + Pp[4096 + j];
                sf += Pp[1024 + j] + Pp[5120 + j];
                sg += Pp[2048 + j];
                so += Pp[3072 + j];
            }
            size_t pxb = ((size_t)tstep * Bn + b) * G4 + j;
            float pi = g_prex[pxb]          + si;
            float pf = g_prex[pxb + Hn]     + sf;
            float pg = g_prex[pxb + 2*Hn]   + sg;
            float po = g_prex[pxb + 3*Hn]   + so;
            float cold = g_c[par][e];

            float ig = sigf(pi);
            float fg = sigf(pf);
            float gv = tanhf(pg);
            float cn = fg * cold + ig * gv;
            float og = sigf(po + cn);
            float hn = og * tanhf(cn);
            float mv = (tstep < lengths[b]) ? 1.f : 0.f;
            hn *= mv; cn *= mv;

            g_c[np][e]  = cn;
            g_ht[np][e] = __float2half_rn(hn);
            g_ct[np][e] = __float2half_rn(cn);

            size_t ob = ((size_t)b * Tn + tstep) * Hn + j;
            out[ob] = hn;
            if (writeC) out[BTH + ob] = cn;
        }

        gridbar();
    }
}

// ---------------------------------------------------------------------------
extern "C" void kernel_launch(void* const* d_in, const int* in_sizes, int n_in,
                              void* d_out, int out_size)
{
    const float* x    = (const float*)d_in[0];
    const float* h0   = (const float*)d_in[1];
    const float* c0   = (const float*)d_in[2];
    const float* wih  = (const float*)d_in[3];
    const float* whh  = (const float*)d_in[4];
    const float* wrec = (const float*)d_in[5];
    const float* bias = (const float*)d_in[6];
    const int* lengths = (const int*)d_in[7];
    float* out = (float*)d_out;
    int writeC = (out_size >= 2 * Bn * Tn * Hn) ? 1 : 0;

    cudaFuncSetAttribute(gemm_prex, cudaFuncAttributeMaxDynamicSharedMemorySize, PSMEM_BYTES);
    cudaFuncSetAttribute(persist_kernel, cudaFuncAttributeMaxDynamicSharedMemorySize, PERS_SMEM);

    pack_w<<<1024, 256>>>(whh, wrec);
    cvt_xw<<<1024, 256>>>(wih, x);
    init_state<<<256, 256>>>(h0, c0);
    gemm_prex<<<dim3(32, 188), 128, PSMEM_BYTES>>>(bias);
    persist_kernel<<<NCTA, NTHR, PERS_SMEM>>>(lengths, out, writeC);
}

// round 9
// speedup vs baseline: 1.4394x; 1.1309x over previous
#include <cuda_runtime.h>
#include <cuda_fp16.h>
#include <cstdint>

#define Bn 64
#define Tn 188
#define In 512
#define Hn 1024
#define G4 (4*Hn)
#define NCTA 144
#define NTHR 256

// ---------------- persistent device scratch (allocation-free rule) ----------
__device__ float  g_prex[(size_t)Tn * Bn * G4];     // [t][b_orig][4H]
__device__ float  g_P[(size_t)3 * Bn * 6144];       // [sp*64+col(bp)][row]
__device__ float  g_c[2][Bn * Hn];                  // fp32 cell state (permuted b)
__device__ __half g_ht[2][Bn * Hn];                 // fp16 hidden (permuted b)
__device__ __half g_ct[2][Bn * Hn];                 // fp16 cell (permuted b)
__device__ uint4  g_Wpk[(size_t)NCTA * 6144];       // packed fp16 W frags per CTA
__device__ uint4  g_Wpih[(size_t)32 * 8192];        // packed fp16 Wih frags per m-tile
__device__ __half g_X[(size_t)Bn * Tn * In];        // x fp16
__device__ int    g_perm[Bn];                       // bp -> original b
__device__ int    g_lens[Bn];                       // sorted desc lengths
__device__ int    g_nj[Tn];                         // ceil(active/8) per step
__device__ unsigned g_bar_ct = 0;
__device__ unsigned g_bar_ep = 0;

__device__ __forceinline__ float sigf(float x){ return 1.f / (1.f + __expf(-x)); }

#define CPA16(dst, src) \
    asm volatile("cp.async.cg.shared.global [%0], [%1], 16;" :: "r"(dst), "l"(src) : "memory")
#define CPC()  asm volatile("cp.async.commit_group;" ::: "memory")
#define CPW(n) asm volatile("cp.async.wait_group %0;" :: "n"(n) : "memory")

#define MMA_F16(acc, a0,a1,a2,a3, b0,b1) \
    asm volatile("mma.sync.aligned.m16n8k16.row.col.f32.f16.f16.f32 " \
        "{%0,%1,%2,%3}, {%4,%5,%6,%7}, {%8,%9}, {%0,%1,%2,%3};" \
        : "+f"((acc)[0]), "+f"((acc)[1]), "+f"((acc)[2]), "+f"((acc)[3]) \
        : "r"(a0), "r"(a1), "r"(a2), "r"(a3), "r"(b0), "r"(b1))

__device__ __forceinline__ uint32_t lds32(uint32_t a){
    uint32_t v; asm volatile("ld.shared.b32 %0, [%1];" : "=r"(v) : "r"(a)); return v;
}
__device__ __forceinline__ uint32_t h2pk(float a, float b){
    __half2 h = __floats2half2_rn(a, b);
    return *(uint32_t*)&h;
}

// ---------------------------------------------------------------------------
// Prep kernels
// ---------------------------------------------------------------------------
__device__ __forceinline__ float Wat(const float* whh, const float* wrec, int r, int c){
    return (r < 4096) ? whh[(size_t)r * Hn + c] : wrec[(size_t)(r - 4096) * Hn + c];
}

// persist W pack (VALIDATED in R8): slot=(((ck*2+kk)*4+w)*2+mt)*32+lane
__global__ void pack_w(const float* __restrict__ whh, const float* __restrict__ wrec){
    const int total = NCTA * 6144;
    for (int s = blockIdx.x * blockDim.x + threadIdx.x; s < total;
         s += gridDim.x * blockDim.x){
        int cta = s / 6144, idx = s % 6144;
        int tt = cta / 3, sp = cta % 3;
        int nch = (sp == 2) ? 8 : 12;
        int lane = idx & 31; int r = idx >> 5;
        int mt = r & 1; r >>= 1;
        int w  = r & 3; r >>= 2;
        int kk = r & 1; int ck = r >> 1;
        if (ck >= nch) continue;
        int g = lane >> 2, t = lane & 3;
        int R0 = tt * 128 + w * 32 + mt * 16 + g;
        int C0 = sp * 384 + ck * 32 + kk * 16 + 2 * t;
        uint4 v;
        v.x = h2pk(Wat(whh, wrec, R0,     C0),     Wat(whh, wrec, R0,     C0 + 1));
        v.y = h2pk(Wat(whh, wrec, R0 + 8, C0),     Wat(whh, wrec, R0 + 8, C0 + 1));
        v.z = h2pk(Wat(whh, wrec, R0,     C0 + 8), Wat(whh, wrec, R0,     C0 + 9));
        v.w = h2pk(Wat(whh, wrec, R0 + 8, C0 + 8), Wat(whh, wrec, R0 + 8, C0 + 9));
        g_Wpk[(size_t)cta * 6144 + idx] = v;
    }
}

// Wih pack: same fragment scheme, nch=16, per 128-row m-tile
__global__ void pack_wih(const float* __restrict__ wih){
    const int total = 32 * 8192;
    for (int s = blockIdx.x * blockDim.x + threadIdx.x; s < total;
         s += gridDim.x * blockDim.x){
        int mtile = s / 8192, idx = s % 8192;
        int lane = idx & 31; int r = idx >> 5;
        int mt = r & 1; r >>= 1;
        int w  = r & 3; r >>= 2;
        int kk = r & 1; int ck = r >> 1;   // 0..15
        int g = lane >> 2, t = lane & 3;
        int R0 = mtile * 128 + w * 32 + mt * 16 + g;
        int C0 = ck * 32 + kk * 16 + 2 * t;
        const float* p0 = wih + (size_t)R0 * In;
        const float* p1 = wih + (size_t)(R0 + 8) * In;
        uint4 v;
        v.x = h2pk(p0[C0],     p0[C0 + 1]);
        v.y = h2pk(p1[C0],     p1[C0 + 1]);
        v.z = h2pk(p0[C0 + 8], p0[C0 + 9]);
        v.w = h2pk(p1[C0 + 8], p1[C0 + 9]);
        g_Wpih[s] = v;
    }
}

__global__ void cvt_x(const float* __restrict__ x){
    const size_t n3 = (size_t)Bn * Tn * In;
    for (size_t i = (size_t)blockIdx.x * blockDim.x + threadIdx.x; i < n3;
         i += (size_t)gridDim.x * blockDim.x)
        g_X[i] = __float2half_rn(x[i]);
}

// rank-sort lengths descending (stable), per-step active tile count
__global__ void prep_sort(const int* __restrict__ lengths){
    __shared__ int sl[Bn];
    int tid = threadIdx.x;
    if (tid < Bn) sl[tid] = lengths[tid];
    __syncthreads();
    if (tid < Bn){
        int L = sl[tid]; int r = 0;
#pragma unroll
        for (int k = 0; k < Bn; k++)
            r += (sl[k] > L) || (sl[k] == L && k < tid);
        g_perm[r] = tid;
        g_lens[r] = L;
    }
    if (tid < Tn){
        int c = 0;
#pragma unroll
        for (int k = 0; k < Bn; k++) c += (sl[k] > tid);
        g_nj[tid] = (c + 7) >> 3;
    }
}

__global__ void init_state(const float* __restrict__ h0, const float* __restrict__ c0){
    int i = blockIdx.x * blockDim.x + threadIdx.x;
    if (i < Bn * Hn){
        int bp = i >> 10, j = i & (Hn - 1);
        int b = g_perm[bp];
        float h = h0[(size_t)b * Hn + j], c = c0[(size_t)b * Hn + j];
        g_c[0][i]  = c;
        g_ht[0][i] = __float2half_rn(h);
        g_ct[0][i] = __float2half_rn(c);
    }
}

// ---------------------------------------------------------------------------
// fp16 input-projection GEMM: D[128,64] = Wih_tile x X_rows^T, K=512
// A fragments direct from packed global; B staged fp16, double-buffered.
// ---------------------------------------------------------------------------
#define PXB 5120
#define PX_SMEM (2 * PXB)

__global__ void __launch_bounds__(128)
gemm_prex(const float* __restrict__ bias)
{
    extern __shared__ __align__(16) char smc[];
    const uint32_t sb = (uint32_t)__cvta_generic_to_shared(smc);
    const int tid = threadIdx.x;
    const int wid = tid >> 5;
    const int lane = tid & 31;
    const int g = lane >> 2, t = lane & 3;
    const int m = blockIdx.x;
    const int nb = blockIdx.y;

    const uint4* __restrict__ Ap = g_Wpih + (size_t)m * 8192;
    const __half* __restrict__ B = g_X + (size_t)nb * 64 * In;

    float acc[2][8][4];
#pragma unroll
    for (int mt = 0; mt < 2; mt++)
#pragma unroll
        for (int j = 0; j < 8; j++)
#pragma unroll
            for (int q = 0; q < 4; q++) acc[mt][j][q] = 0.f;

#define PX_ST(buf, ck) do {                                                    \
        for (int u = tid; u < 256; u += 128){                                  \
            int rr = u >> 2, uu = u & 3;                                       \
            CPA16(sb + (buf) * PXB + rr * 80 + uu * 16,                        \
                  B + (size_t)rr * In + (ck) * 32 + uu * 8);                   \
        }                                                                      \
    } while (0)

#define PX_LDA(dst, ck) do {                                                   \
        (dst)[0][0] = Ap[((((ck) * 2 + 0) * 4 + wid) * 2 + 0) * 32 + lane];    \
        (dst)[0][1] = Ap[((((ck) * 2 + 0) * 4 + wid) * 2 + 1) * 32 + lane];    \
        (dst)[1][0] = Ap[((((ck) * 2 + 1) * 4 + wid) * 2 + 0) * 32 + lane];    \
        (dst)[1][1] = Ap[((((ck) * 2 + 1) * 4 + wid) * 2 + 1) * 32 + lane];    \
    } while (0)

    PX_ST(0, 0); CPC();
    uint4 av[2][2];
    PX_LDA(av, 0);

#pragma unroll 1
    for (int ch = 0; ch < 16; ch++){
        CPW(0);
        __syncthreads();
        if (ch + 1 < 16){ PX_ST((ch + 1) & 1, ch + 1); CPC(); }
        uint4 nx[2][2];
        if (ch + 1 < 16) PX_LDA(nx, ch + 1);

        const uint32_t Bb = sb + (ch & 1) * PXB;
#pragma unroll
        for (int kk = 0; kk < 2; kk++){
            uint32_t b[8][2];
#pragma unroll
            for (int j = 0; j < 8; j++){
                uint32_t bbase = Bb + (j * 8 + g) * 80 + kk * 32 + t * 4;
                b[j][0] = lds32(bbase);
                b[j][1] = lds32(bbase + 16);
            }
#pragma unroll
            for (int mt = 0; mt < 2; mt++){
                uint4 a = av[kk][mt];
#pragma unroll
                for (int j = 0; j < 8; j++)
                    MMA_F16(acc[mt][j], a.x, a.y, a.z, a.w, b[j][0], b[j][1]);
            }
        }
        if (ch + 1 < 16){
            av[0][0] = nx[0][0]; av[0][1] = nx[0][1];
            av[1][0] = nx[1][0]; av[1][1] = nx[1][1];
        }
    }

#pragma unroll
    for (int mt = 0; mt < 2; mt++){
        int rowb = m * 128 + wid * 32 + mt * 16;
        float bs0 = bias[rowb + g];
        float bs1 = bias[rowb + g + 8];
#pragma unroll
        for (int j = 0; j < 8; j++)
#pragma unroll
            for (int q = 0; q < 4; q++){
                int row = rowb + g + (q >> 1) * 8;
                int n   = nb * 64 + j * 8 + t * 2 + (q & 1);
                int bq  = n / Tn, tq = n - bq * Tn;
                g_prex[((size_t)tq * Bn + bq) * G4 + row] =
                    acc[mt][j][q] + ((q >> 1) ? bs1 : bs0);
            }
    }
}

// ---------------------------------------------------------------------------
// Persistent recurrent kernel (R8 structure + batch compaction)
// ---------------------------------------------------------------------------
#define SWB  98304
#define BBUF 5120
#define PERS_SMEM (SWB + 2 * BBUF)

__device__ __forceinline__ void gridbar(){
    __threadfence();
    __syncthreads();
    if (threadIdx.x == 0){
        unsigned e = *(volatile unsigned*)&g_bar_ep;
        unsigned v = atomicAdd(&g_bar_ct, 1u);
        if (v == NCTA - 1){
            g_bar_ct = 0;
            __threadfence();
            atomicAdd(&g_bar_ep, 1u);
        } else {
            while (*(volatile unsigned*)&g_bar_ep == e) __nanosleep(64);
        }
    }
    __syncthreads();
    __threadfence();
}

__global__ void __launch_bounds__(NTHR, 1)
persist_kernel(float* __restrict__ out, int writeC)
{
    extern __shared__ __align__(16) char smc[];
    const uint32_t sb = (uint32_t)__cvta_generic_to_shared(smc);
    const uint4* sW4 = (const uint4*)smc;
    const int tid  = threadIdx.x;
    const int wid  = tid >> 5;
    const int lane = tid & 31;
    const int g = lane >> 2, t = lane & 3;
    const int cta  = blockIdx.x;
    const int tt   = cta / 3;
    const int sp   = cta % 3;
    const int spk0 = sp * 384;
    const int nch  = (sp == 2) ? 8 : 12;

    // one-time load of packed fp16 W tile
    {
        const uint4* src = &g_Wpk[(size_t)cta * 6144];
        int n4 = nch * 512;
        for (int u = tid; u < n4; u += NTHR)
            CPA16(sb + u * 16, (const char*)(src + u));
        CPC(); CPW(0);
        __syncthreads();
    }

    const size_t BTH = (size_t)Bn * Tn * Hn;

#pragma unroll 1
    for (int tstep = 0; tstep < Tn; tstep++){
        const int par = tstep & 1, np = par ^ 1;
        const int nj = __ldg(&g_nj[tstep]);        // active n-tiles (0..8)
        const int ract = nj << 3;                  // active batch rows
        const __half* __restrict__ Bsrc = (tt < 32) ? g_ht[par] : g_ct[par];

        float acc[2][8][4];
#pragma unroll
        for (int mt = 0; mt < 2; mt++)
#pragma unroll
            for (int j = 0; j < 8; j++)
#pragma unroll
                for (int q = 0; q < 4; q++) acc[mt][j][q] = 0.f;

#define ST_B16(buf, ck) do {                                                   \
        int rr = tid >> 2, uu = tid & 3;                                       \
        if (rr < ract)                                                         \
            CPA16(sb + SWB + (buf) * BBUF + rr * 80 + uu * 16,                 \
                  Bsrc + (size_t)rr * Hn + spk0 + (ck) * 32 + uu * 8);         \
    } while (0)

        if (nj > 0){
            ST_B16(0, 0); CPC();

#pragma unroll 1
            for (int ck = 0; ck < nch; ck++){
                CPW(0);
                __syncthreads();
                if (ck + 1 < nch){ ST_B16((ck + 1) & 1, ck + 1); CPC(); }

                if (wid < 4){
                    const uint32_t Bb = sb + SWB + (ck & 1) * BBUF;
#pragma unroll
                    for (int kk = 0; kk < 2; kk++){
                        uint32_t b[8][2];
#pragma unroll
                        for (int j = 0; j < 8; j++) if (j < nj){
                            uint32_t bbase = Bb + (j * 8 + g) * 80 + kk * 32 + t * 4;
                            b[j][0] = lds32(bbase);
                            b[j][1] = lds32(bbase + 16);
                        }
#pragma unroll
                        for (int mt = 0; mt < 2; mt++){
                            uint4 av = sW4[((((ck * 2 + kk) * 4 + wid) * 2 + mt) * 32) + lane];
#pragma unroll
                            for (int j = 0; j < 8; j++) if (j < nj)
                                MMA_F16(acc[mt][j], av.x, av.y, av.z, av.w,
                                        b[j][0], b[j][1]);
                        }
                    }
                }
            }

            // epilogue: partials -> g_P[(sp*64+col)][row], active cols only
            if (wid < 4){
#pragma unroll
                for (int mt = 0; mt < 2; mt++)
#pragma unroll
                    for (int j = 0; j < 8; j++) if (j < nj)
#pragma unroll
                        for (int q = 0; q < 4; q++){
                            int row = tt * 128 + wid * 32 + mt * 16 + g + (q >> 1) * 8;
                            int col = j * 8 + t * 2 + (q & 1);
                            g_P[((size_t)(sp * 64 + col)) * 6144 + row] = acc[mt][j][q];
                        }
            }
        }

        gridbar();

        // fused cell phase (permuted batch order)
        for (int e = cta * NTHR + tid; e < Bn * Hn; e += NCTA * NTHR){
            int j  = e & (Hn - 1);
            int bp = e >> 10;
            int borig = __ldg(&g_perm[bp]);
            int L     = __ldg(&g_lens[bp]);
            size_t ob = ((size_t)borig * Tn + tstep) * Hn + j;

            if (tstep < L){
                float si = 0.f, sf = 0.f, sg = 0.f, so = 0.f;
#pragma unroll
                for (int s2 = 0; s2 < 3; s2++){
                    const float* Pp = g_P + ((size_t)(s2 * 64 + bp)) * 6144;
                    si += Pp[j]        + Pp[4096 + j];
                    sf += Pp[1024 + j] + Pp[5120 + j];
                    sg += Pp[2048 + j];
                    so += Pp[3072 + j];
                }
                size_t pxb = ((size_t)tstep * Bn + borig) * G4 + j;
                float pi = g_prex[pxb]          + si;
                float pf = g_prex[pxb + Hn]     + sf;
                float pg = g_prex[pxb + 2*Hn]   + sg;
                float po = g_prex[pxb + 3*Hn]   + so;
                float cold = g_c[par][e];

                float ig = sigf(pi);
                float fg = sigf(pf);
                float gv = tanhf(pg);
                float cn = fg * cold + ig * gv;
                float og = sigf(po + cn);
                float hn = og * tanhf(cn);

                g_c[np][e]  = cn;
                g_ht[np][e] = __float2half_rn(hn);
                g_ct[np][e] = __float2half_rn(cn);

                out[ob] = hn;
                if (writeC) out[BTH + ob] = cn;
            } else {
                g_c[np][e]  = 0.f;
                g_ht[np][e] = __float2half_rn(0.f);
                g_ct[np][e] = __float2half_rn(0.f);
                out[ob] = 0.f;
                if (writeC) out[BTH + ob] = 0.f;
            }
        }

        gridbar();
    }
}

// ---------------------------------------------------------------------------
extern "C" void kernel_launch(void* const* d_in, const int* in_sizes, int n_in,
                              void* d_out, int out_size)
{
    const float* x    = (const float*)d_in[0];
    const float* h0   = (const float*)d_in[1];
    const float* c0   = (const float*)d_in[2];
    const float* wih  = (const float*)d_in[3];
    const float* whh  = (const float*)d_in[4];
    const float* wrec = (const float*)d_in[5];
    const float* bias = (const float*)d_in[6];
    const int* lengths = (const int*)d_in[7];
    float* out = (float*)d_out;
    int writeC = (out_size >= 2 * Bn * Tn * Hn) ? 1 : 0;

    cudaFuncSetAttribute(gemm_prex, cudaFuncAttributeMaxDynamicSharedMemorySize, PX_SMEM);
    cudaFuncSetAttribute(persist_kernel, cudaFuncAttributeMaxDynamicSharedMemorySize, PERS_SMEM);

    prep_sort<<<1, 256>>>(lengths);
    pack_w<<<1024, 256>>>(whh, wrec);
    pack_wih<<<512, 256>>>(wih);
    cvt_x<<<1024, 256>>>(x);
    init_state<<<256, 256>>>(h0, c0);
    gemm_prex<<<dim3(32, 188), 128, PX_SMEM>>>(bias);
    persist_kernel<<<NCTA, NTHR, PERS_SMEM>>>(out, writeC);
}

// round 10
// speedup vs baseline: 1.4729x; 1.0233x over previous
#include <cuda_runtime.h>
#include <cuda_fp16.h>
#include <cstdint>

#define Bn 64
#define Tn 188
#define In 512
#define Hn 1024
#define G4 (4*Hn)
#define NCTA 144
#define NTHR 256

// ---------------- persistent device scratch (allocation-free rule) ----------
__device__ float  g_prex[(size_t)Tn * Bn * G4];     // [t][b_orig][4H]
__device__ float  g_P[(size_t)3 * Bn * 6144];       // [sp*64+col(bp)][row]
__device__ float  g_c[2][Bn * Hn];                  // fp32 cell state (permuted b)
__device__ __half g_ht[2][Bn * Hn];                 // fp16 hidden (permuted b)
__device__ __half g_ct[2][Bn * Hn];                 // fp16 cell (permuted b)
__device__ uint4  g_Wpk[(size_t)NCTA * 6144];       // packed fp16 W frags per CTA
__device__ uint4  g_Wpih[(size_t)32 * 8192];        // packed fp16 Wih frags per m-tile
__device__ __half g_X[(size_t)Bn * Tn * In];        // x fp16
__device__ int    g_perm[Bn];                       // bp -> original b
__device__ int    g_na[Tn];                         // exact active count per step
__device__ int    g_nj[Tn];                         // ceil(active/8) per step
__device__ unsigned g_bar_ct = 0;
__device__ unsigned g_bar_ep = 0;

__device__ __forceinline__ float sigf(float x){ return 1.f / (1.f + __expf(-x)); }

#define CPA16(dst, src) \
    asm volatile("cp.async.cg.shared.global [%0], [%1], 16;" :: "r"(dst), "l"(src) : "memory")
#define CPC()  asm volatile("cp.async.commit_group;" ::: "memory")
#define CPW(n) asm volatile("cp.async.wait_group %0;" :: "n"(n) : "memory")

#define MMA_F16(acc, a0,a1,a2,a3, b0,b1) \
    asm volatile("mma.sync.aligned.m16n8k16.row.col.f32.f16.f16.f32 " \
        "{%0,%1,%2,%3}, {%4,%5,%6,%7}, {%8,%9}, {%0,%1,%2,%3};" \
        : "+f"((acc)[0]), "+f"((acc)[1]), "+f"((acc)[2]), "+f"((acc)[3]) \
        : "r"(a0), "r"(a1), "r"(a2), "r"(a3), "r"(b0), "r"(b1))

__device__ __forceinline__ uint32_t lds32(uint32_t a){
    uint32_t v; asm volatile("ld.shared.b32 %0, [%1];" : "=r"(v) : "r"(a)); return v;
}
__device__ __forceinline__ uint32_t h2pk(float a, float b){
    __half2 h = __floats2half2_rn(a, b);
    return *(uint32_t*)&h;
}

// ---------------------------------------------------------------------------
// Prep kernels
// ---------------------------------------------------------------------------
__device__ __forceinline__ float Wat(const float* whh, const float* wrec, int r, int c){
    return (r < 4096) ? whh[(size_t)r * Hn + c] : wrec[(size_t)(r - 4096) * Hn + c];
}

// persist W pack (VALIDATED R8): slot=(((ck*2+kk)*4+w)*2+mt)*32+lane
__global__ void pack_w(const float* __restrict__ whh, const float* __restrict__ wrec){
    const int total = NCTA * 6144;
    for (int s = blockIdx.x * blockDim.x + threadIdx.x; s < total;
         s += gridDim.x * blockDim.x){
        int cta = s / 6144, idx = s % 6144;
        int tt = cta / 3, sp = cta % 3;
        int nch = (sp == 2) ? 8 : 12;
        int lane = idx & 31; int r = idx >> 5;
        int mt = r & 1; r >>= 1;
        int w  = r & 3; r >>= 2;
        int kk = r & 1; int ck = r >> 1;
        if (ck >= nch) continue;
        int g = lane >> 2, t = lane & 3;
        int R0 = tt * 128 + w * 32 + mt * 16 + g;
        int C0 = sp * 384 + ck * 32 + kk * 16 + 2 * t;
        uint4 v;
        v.x = h2pk(Wat(whh, wrec, R0,     C0),     Wat(whh, wrec, R0,     C0 + 1));
        v.y = h2pk(Wat(whh, wrec, R0 + 8, C0),     Wat(whh, wrec, R0 + 8, C0 + 1));
        v.z = h2pk(Wat(whh, wrec, R0,     C0 + 8), Wat(whh, wrec, R0,     C0 + 9));
        v.w = h2pk(Wat(whh, wrec, R0 + 8, C0 + 8), Wat(whh, wrec, R0 + 8, C0 + 9));
        g_Wpk[(size_t)cta * 6144 + idx] = v;
    }
}

// Wih pack (VALIDATED R9)
__global__ void pack_wih(const float* __restrict__ wih){
    const int total = 32 * 8192;
    for (int s = blockIdx.x * blockDim.x + threadIdx.x; s < total;
         s += gridDim.x * blockDim.x){
        int mtile = s / 8192, idx = s % 8192;
        int lane = idx & 31; int r = idx >> 5;
        int mt = r & 1; r >>= 1;
        int w  = r & 3; r >>= 2;
        int kk = r & 1; int ck = r >> 1;
        int g = lane >> 2, t = lane & 3;
        int R0 = mtile * 128 + w * 32 + mt * 16 + g;
        int C0 = ck * 32 + kk * 16 + 2 * t;
        const float* p0 = wih + (size_t)R0 * In;
        const float* p1 = wih + (size_t)(R0 + 8) * In;
        uint4 v;
        v.x = h2pk(p0[C0],     p0[C0 + 1]);
        v.y = h2pk(p1[C0],     p1[C0 + 1]);
        v.z = h2pk(p0[C0 + 8], p0[C0 + 9]);
        v.w = h2pk(p1[C0 + 8], p1[C0 + 9]);
        g_Wpih[s] = v;
    }
}

__global__ void cvt_x(const float* __restrict__ x){
    const size_t n3 = (size_t)Bn * Tn * In;
    for (size_t i = (size_t)blockIdx.x * blockDim.x + threadIdx.x; i < n3;
         i += (size_t)gridDim.x * blockDim.x)
        g_X[i] = __float2half_rn(x[i]);
}

__global__ void out_zero(float* __restrict__ out, size_t n4){
    // n4 = out elements / 4
    float4 z = make_float4(0.f, 0.f, 0.f, 0.f);
    for (size_t i = (size_t)blockIdx.x * blockDim.x + threadIdx.x; i < n4;
         i += (size_t)gridDim.x * blockDim.x)
        ((float4*)out)[i] = z;
}

// rank-sort lengths descending (stable), per-step active counts
__global__ void prep_sort(const int* __restrict__ lengths){
    __shared__ int sl[Bn];
    int tid = threadIdx.x;
    if (tid < Bn) sl[tid] = lengths[tid];
    __syncthreads();
    if (tid < Bn){
        int L = sl[tid]; int r = 0;
#pragma unroll
        for (int k = 0; k < Bn; k++)
            r += (sl[k] > L) || (sl[k] == L && k < tid);
        g_perm[r] = tid;
    }
    if (tid < Tn){
        int c = 0;
#pragma unroll
        for (int k = 0; k < Bn; k++) c += (sl[k] > tid);
        g_na[tid] = c;
        g_nj[tid] = (c + 7) >> 3;
    }
}

__global__ void init_state(const float* __restrict__ h0, const float* __restrict__ c0){
    int i = blockIdx.x * blockDim.x + threadIdx.x;
    if (i < Bn * Hn){
        int bp = i >> 10, j = i & (Hn - 1);
        int b = g_perm[bp];
        float h = h0[(size_t)b * Hn + j], c = c0[(size_t)b * Hn + j];
        g_c[0][i]  = c;
        g_ht[0][i] = __float2half_rn(h);
        g_ct[0][i] = __float2half_rn(c);
    }
}

// ---------------------------------------------------------------------------
// fp16 input-projection GEMM (VALIDATED R9) + dead-tile skip
// ---------------------------------------------------------------------------
#define PXB 5120
#define PX_SMEM (2 * PXB)

__global__ void __launch_bounds__(128)
gemm_prex(const float* __restrict__ bias, const int* __restrict__ lengths)
{
    const int nb = blockIdx.y;
    {   // dead-tile check: tile columns n in [nb*64, nb*64+64)
        int n0 = nb * 64;
        int b0 = n0 / Tn, t0 = n0 - b0 * Tn;
        bool cross = ((n0 + 63) / Tn) != b0;   // crosses into next batch (min tq = 0 < len)
        if (!cross && t0 >= __ldg(&lengths[b0])) return;
    }

    extern __shared__ __align__(16) char smc[];
    const uint32_t sb = (uint32_t)__cvta_generic_to_shared(smc);
    const int tid = threadIdx.x;
    const int wid = tid >> 5;
    const int lane = tid & 31;
    const int g = lane >> 2, t = lane & 3;
    const int m = blockIdx.x;

    const uint4* __restrict__ Ap = g_Wpih + (size_t)m * 8192;
    const __half* __restrict__ B = g_X + (size_t)nb * 64 * In;

    float acc[2][8][4];
#pragma unroll
    for (int mt = 0; mt < 2; mt++)
#pragma unroll
        for (int j = 0; j < 8; j++)
#pragma unroll
            for (int q = 0; q < 4; q++) acc[mt][j][q] = 0.f;

#define PX_ST(buf, ck) do {                                                    \
        for (int u = tid; u < 256; u += 128){                                  \
            int rr = u >> 2, uu = u & 3;                                       \
            CPA16(sb + (buf) * PXB + rr * 80 + uu * 16,                        \
                  B + (size_t)rr * In + (ck) * 32 + uu * 8);                   \
        }                                                                      \
    } while (0)

#define PX_LDA(dst, ck) do {                                                   \
        (dst)[0][0] = Ap[((((ck) * 2 + 0) * 4 + wid) * 2 + 0) * 32 + lane];    \
        (dst)[0][1] = Ap[((((ck) * 2 + 0) * 4 + wid) * 2 + 1) * 32 + lane];    \
        (dst)[1][0] = Ap[((((ck) * 2 + 1) * 4 + wid) * 2 + 0) * 32 + lane];    \
        (dst)[1][1] = Ap[((((ck) * 2 + 1) * 4 + wid) * 2 + 1) * 32 + lane];    \
    } while (0)

    PX_ST(0, 0); CPC();
    uint4 av[2][2];
    PX_LDA(av, 0);

#pragma unroll 1
    for (int ch = 0; ch < 16; ch++){
        CPW(0);
        __syncthreads();
        if (ch + 1 < 16){ PX_ST((ch + 1) & 1, ch + 1); CPC(); }
        uint4 nx[2][2];
        if (ch + 1 < 16) PX_LDA(nx, ch + 1);

        const uint32_t Bb = sb + (ch & 1) * PXB;
#pragma unroll
        for (int kk = 0; kk < 2; kk++){
            uint32_t b[8][2];
#pragma unroll
            for (int j = 0; j < 8; j++){
                uint32_t bbase = Bb + (j * 8 + g) * 80 + kk * 32 + t * 4;
                b[j][0] = lds32(bbase);
                b[j][1] = lds32(bbase + 16);
            }
#pragma unroll
            for (int mt = 0; mt < 2; mt++){
                uint4 a = av[kk][mt];
#pragma unroll
                for (int j = 0; j < 8; j++)
                    MMA_F16(acc[mt][j], a.x, a.y, a.z, a.w, b[j][0], b[j][1]);
            }
        }
        if (ch + 1 < 16){
            av[0][0] = nx[0][0]; av[0][1] = nx[0][1];
            av[1][0] = nx[1][0]; av[1][1] = nx[1][1];
        }
    }

#pragma unroll
    for (int mt = 0; mt < 2; mt++){
        int rowb = m * 128 + wid * 32 + mt * 16;
        float bs0 = bias[rowb + g];
        float bs1 = bias[rowb + g + 8];
#pragma unroll
        for (int j = 0; j < 8; j++)
#pragma unroll
            for (int q = 0; q < 4; q++){
                int row = rowb + g + (q >> 1) * 8;
                int n   = blockIdx.y * 64 + j * 8 + t * 2 + (q & 1);
                int bq  = n / Tn, tq = n - bq * Tn;
                g_prex[((size_t)tq * Bn + bq) * G4 + row] =
                    acc[mt][j][q] + ((q >> 1) ? bs1 : bs0);
            }
    }
}

// ---------------------------------------------------------------------------
// Persistent recurrent kernel
// ---------------------------------------------------------------------------
#define SWB  98304
#define BBUF 5120
#define PERS_SMEM (SWB + 2 * BBUF)

__device__ __forceinline__ void gridbar(){
    __threadfence();
    __syncthreads();
    if (threadIdx.x == 0){
        unsigned e = *(volatile unsigned*)&g_bar_ep;
        unsigned v = atomicAdd(&g_bar_ct, 1u);
        if (v == NCTA - 1){
            g_bar_ct = 0;
            __threadfence();
            atomicAdd(&g_bar_ep, 1u);
        } else {
            while (*(volatile unsigned*)&g_bar_ep == e) { }
        }
    }
    __syncthreads();
    __threadfence();
}

__global__ void __launch_bounds__(NTHR, 1)
persist_kernel(float* __restrict__ out, int writeC)
{
    extern __shared__ __align__(16) char smc[];
    const uint32_t sb = (uint32_t)__cvta_generic_to_shared(smc);
    const uint4* sW4 = (const uint4*)smc;
    const int tid  = threadIdx.x;
    const int wid  = tid >> 5;
    const int lane = tid & 31;
    const int g = lane >> 2, t = lane & 3;
    const int cta  = blockIdx.x;
    const int tt   = cta / 3;
    const int sp   = cta % 3;
    const int spk0 = sp * 384;
    const int nch  = (sp == 2) ? 8 : 12;

    // one-time load of packed fp16 W tile
    {
        const uint4* src = &g_Wpk[(size_t)cta * 6144];
        int n4 = nch * 512;
        for (int u = tid; u < n4; u += NTHR)
            CPA16(sb + u * 16, (const char*)(src + u));
        CPC(); CPW(0);
        __syncthreads();
    }

    const size_t BTH = (size_t)Bn * Tn * Hn;

#pragma unroll 1
    for (int tstep = 0; tstep < Tn; tstep++){
        const int par = tstep & 1, np = par ^ 1;
        const int na = __ldg(&g_na[tstep]);        // exact active batches
        const int nj = (na + 7) >> 3;              // active n-tiles
        if (nj == 0) break;                        // monotone: nothing left ever
        const int ract = nj << 3;
        const __half* __restrict__ Bsrc = (tt < 32) ? g_ht[par] : g_ct[par];

        float acc[2][8][4];
#pragma unroll
        for (int mt = 0; mt < 2; mt++)
#pragma unroll
            for (int j = 0; j < 8; j++)
#pragma unroll
                for (int q = 0; q < 4; q++) acc[mt][j][q] = 0.f;

#define ST_B16(buf, ck) do {                                                   \
        int rr = tid >> 2, uu = tid & 3;                                       \
        if (rr < ract)                                                         \
            CPA16(sb + SWB + (buf) * BBUF + rr * 80 + uu * 16,                 \
                  Bsrc + (size_t)rr * Hn + spk0 + (ck) * 32 + uu * 8);         \
    } while (0)

        ST_B16(0, 0); CPC();

#pragma unroll 1
        for (int ck = 0; ck < nch; ck++){
            CPW(0);
            __syncthreads();
            if (ck + 1 < nch){ ST_B16((ck + 1) & 1, ck + 1); CPC(); }

            if (wid < 4){
                const uint32_t Bb = sb + SWB + (ck & 1) * BBUF;
#pragma unroll
                for (int kk = 0; kk < 2; kk++){
                    uint32_t b[8][2];
#pragma unroll
                    for (int j = 0; j < 8; j++) if (j < nj){
                        uint32_t bbase = Bb + (j * 8 + g) * 80 + kk * 32 + t * 4;
                        b[j][0] = lds32(bbase);
                        b[j][1] = lds32(bbase + 16);
                    }
#pragma unroll
                    for (int mt = 0; mt < 2; mt++){
                        uint4 av = sW4[((((ck * 2 + kk) * 4 + wid) * 2 + mt) * 32) + lane];
#pragma unroll
                        for (int j = 0; j < 8; j++) if (j < nj)
                            MMA_F16(acc[mt][j], av.x, av.y, av.z, av.w,
                                    b[j][0], b[j][1]);
                    }
                }
            }
        }

        // epilogue: partials -> g_P[(sp*64+col)][row], active tiles only
        if (wid < 4){
#pragma unroll
            for (int mt = 0; mt < 2; mt++)
#pragma unroll
                for (int j = 0; j < 8; j++) if (j < nj)
#pragma unroll
                    for (int q = 0; q < 4; q++){
                        int row = tt * 128 + wid * 32 + mt * 16 + g + (q >> 1) * 8;
                        int col = j * 8 + t * 2 + (q & 1);
                        g_P[((size_t)(sp * 64 + col)) * 6144 + row] = acc[mt][j][q];
                    }
        }

        gridbar();

        // fused cell phase — ACTIVE batches only (sorted desc => bp < na)
        const int ncell = na << 10;
        for (int e = cta * NTHR + tid; e < ncell; e += NCTA * NTHR){
            int j  = e & (Hn - 1);
            int bp = e >> 10;
            int borig = __ldg(&g_perm[bp]);

            float si = 0.f, sf = 0.f, sg = 0.f, so = 0.f;
#pragma unroll
            for (int s2 = 0; s2 < 3; s2++){
                const float* Pp = g_P + ((size_t)(s2 * 64 + bp)) * 6144;
                si += Pp[j]        + Pp[4096 + j];
                sf += Pp[1024 + j] + Pp[5120 + j];
                sg += Pp[2048 + j];
                so += Pp[3072 + j];
            }
            size_t pxb = ((size_t)tstep * Bn + borig) * G4 + j;
            float pi = g_prex[pxb]          + si;
            float pf = g_prex[pxb + Hn]     + sf;
            float pg = g_prex[pxb + 2*Hn]   + sg;
            float po = g_prex[pxb + 3*Hn]   + so;
            float cold = g_c[par][e];

            float ig = sigf(pi);
            float fg = sigf(pf);
            float gv = tanhf(pg);
            float cn = fg * cold + ig * gv;
            float og = sigf(po + cn);
            float hn = og * tanhf(cn);

            g_c[np][e]  = cn;
            g_ht[np][e] = __float2half_rn(hn);
            g_ct[np][e] = __float2half_rn(cn);

            size_t ob = ((size_t)borig * Tn + tstep) * Hn + j;
            out[ob] = hn;
            if (writeC) out[BTH + ob] = cn;
        }

        gridbar();
    }
}

// ---------------------------------------------------------------------------
extern "C" void kernel_launch(void* const* d_in, const int* in_sizes, int n_in,
                              void* d_out, int out_size)
{
    const float* x    = (const float*)d_in[0];
    const float* h0   = (const float*)d_in[1];
    const float* c0   = (const float*)d_in[2];
    const float* wih  = (const float*)d_in[3];
    const float* whh  = (const float*)d_in[4];
    const float* wrec = (const float*)d_in[5];
    const float* bias = (const float*)d_in[6];
    const int* lengths = (const int*)d_in[7];
    float* out = (float*)d_out;
    int writeC = (out_size >= 2 * Bn * Tn * Hn) ? 1 : 0;

    cudaFuncSetAttribute(gemm_prex, cudaFuncAttributeMaxDynamicSharedMemorySize, PX_SMEM);
    cudaFuncSetAttribute(persist_kernel, cudaFuncAttributeMaxDynamicSharedMemorySize, PERS_SMEM);

    prep_sort<<<1, 256>>>(lengths);
    pack_w<<<1024, 256>>>(whh, wrec);
    pack_wih<<<512, 256>>>(wih);
    cvt_x<<<1024, 256>>>(x);
    out_zero<<<1024, 256>>>(out, (size_t)out_size / 4);
    init_state<<<256, 256>>>(h0, c0);
    gemm_prex<<<dim3(32, 188), 128, PX_SMEM>>>(bias, lengths);
    persist_kernel<<<NCTA, NTHR, PERS_SMEM>>>(out, writeC);
}

// round 11
// speedup vs baseline: 1.6077x; 1.0916x over previous
#include <cuda_runtime.h>
#include <cuda_fp16.h>
#include <cstdint>

#define Bn 64
#define Tn 188
#define In 512
#define Hn 1024
#define G4 (4*Hn)
#define NCTA 144
#define NTHR 256

// ---------------- persistent device scratch (allocation-free rule) ----------
__device__ float  g_prex[(size_t)Tn * Bn * G4];     // [t][b_orig][4H]
__device__ float  g_P[(size_t)3 * Bn * 6144];       // [sp*64+col(bp)][row]
__device__ float  g_c[2][Bn * Hn];                  // fp32 cell state (permuted b)
__device__ __half g_ht[2][Bn * Hn];                 // fp16 hidden (permuted b)
__device__ __half g_ct[2][Bn * Hn];                 // fp16 cell (permuted b)
__device__ uint4  g_Wpk[(size_t)NCTA * 6144];       // packed fp16 W frags per CTA
__device__ uint4  g_Wpih[(size_t)32 * 8192];        // packed fp16 Wih frags per m-tile
__device__ __half g_X[(size_t)Bn * Tn * In];        // x fp16
__device__ int    g_perm[Bn];                       // bp -> original b
__device__ int    g_na[Tn];                         // exact active count per step
__device__ unsigned g_bar_ct = 0;
__device__ unsigned g_bar_ep = 0;

__device__ __forceinline__ float sigf(float x){ return 1.f / (1.f + __expf(-x)); }

#define CPA16(dst, src) \
    asm volatile("cp.async.cg.shared.global [%0], [%1], 16;" :: "r"(dst), "l"(src) : "memory")
#define CPC()  asm volatile("cp.async.commit_group;" ::: "memory")
#define CPW(n) asm volatile("cp.async.wait_group %0;" :: "n"(n) : "memory")

#define MMA_F16(acc, a0,a1,a2,a3, b0,b1) \
    asm volatile("mma.sync.aligned.m16n8k16.row.col.f32.f16.f16.f32 " \
        "{%0,%1,%2,%3}, {%4,%5,%6,%7}, {%8,%9}, {%0,%1,%2,%3};" \
        : "+f"((acc)[0]), "+f"((acc)[1]), "+f"((acc)[2]), "+f"((acc)[3]) \
        : "r"(a0), "r"(a1), "r"(a2), "r"(a3), "r"(b0), "r"(b1))

__device__ __forceinline__ uint32_t lds32(uint32_t a){
    uint32_t v; asm volatile("ld.shared.b32 %0, [%1];" : "=r"(v) : "r"(a)); return v;
}
__device__ __forceinline__ uint32_t h2pk(float a, float b){
    __half2 h = __floats2half2_rn(a, b);
    return *(uint32_t*)&h;
}

// ---------------------------------------------------------------------------
// Prep kernels
// ---------------------------------------------------------------------------
__device__ __forceinline__ float Wat(const float* whh, const float* wrec, int r, int c){
    return (r < 4096) ? whh[(size_t)r * Hn + c] : wrec[(size_t)(r - 4096) * Hn + c];
}

// persist W pack (VALIDATED R8): slot=(((ck*2+kk)*4+w)*2+mt)*32+lane
__global__ void pack_w(const float* __restrict__ whh, const float* __restrict__ wrec){
    const int total = NCTA * 6144;
    for (int s = blockIdx.x * blockDim.x + threadIdx.x; s < total;
         s += gridDim.x * blockDim.x){
        int cta = s / 6144, idx = s % 6144;
        int tt = cta / 3, sp = cta % 3;
        int nch = (sp == 2) ? 8 : 12;
        int lane = idx & 31; int r = idx >> 5;
        int mt = r & 1; r >>= 1;
        int w  = r & 3; r >>= 2;
        int kk = r & 1; int ck = r >> 1;
        if (ck >= nch) continue;
        int g = lane >> 2, t = lane & 3;
        int R0 = tt * 128 + w * 32 + mt * 16 + g;
        int C0 = sp * 384 + ck * 32 + kk * 16 + 2 * t;
        uint4 v;
        v.x = h2pk(Wat(whh, wrec, R0,     C0),     Wat(whh, wrec, R0,     C0 + 1));
        v.y = h2pk(Wat(whh, wrec, R0 + 8, C0),     Wat(whh, wrec, R0 + 8, C0 + 1));
        v.z = h2pk(Wat(whh, wrec, R0,     C0 + 8), Wat(whh, wrec, R0,     C0 + 9));
        v.w = h2pk(Wat(whh, wrec, R0 + 8, C0 + 8), Wat(whh, wrec, R0 + 8, C0 + 9));
        g_Wpk[(size_t)cta * 6144 + idx] = v;
    }
}

// Wih pack (VALIDATED R9)
__global__ void pack_wih(const float* __restrict__ wih){
    const int total = 32 * 8192;
    for (int s = blockIdx.x * blockDim.x + threadIdx.x; s < total;
         s += gridDim.x * blockDim.x){
        int mtile = s / 8192, idx = s % 8192;
        int lane = idx & 31; int r = idx >> 5;
        int mt = r & 1; r >>= 1;
        int w  = r & 3; r >>= 2;
        int kk = r & 1; int ck = r >> 1;
        int g = lane >> 2, t = lane & 3;
        int R0 = mtile * 128 + w * 32 + mt * 16 + g;
        int C0 = ck * 32 + kk * 16 + 2 * t;
        const float* p0 = wih + (size_t)R0 * In;
        const float* p1 = wih + (size_t)(R0 + 8) * In;
        uint4 v;
        v.x = h2pk(p0[C0],     p0[C0 + 1]);
        v.y = h2pk(p1[C0],     p1[C0 + 1]);
        v.z = h2pk(p0[C0 + 8], p0[C0 + 9]);
        v.w = h2pk(p1[C0 + 8], p1[C0 + 9]);
        g_Wpih[s] = v;
    }
}

__global__ void cvt_x(const float* __restrict__ x){
    const size_t n3 = (size_t)Bn * Tn * In;
    for (size_t i = (size_t)blockIdx.x * blockDim.x + threadIdx.x; i < n3;
         i += (size_t)gridDim.x * blockDim.x)
        g_X[i] = __float2half_rn(x[i]);
}

__global__ void out_zero(float* __restrict__ out, size_t n4){
    float4 z = make_float4(0.f, 0.f, 0.f, 0.f);
    for (size_t i = (size_t)blockIdx.x * blockDim.x + threadIdx.x; i < n4;
         i += (size_t)gridDim.x * blockDim.x)
        ((float4*)out)[i] = z;
}

// rank-sort lengths descending (stable), per-step active counts
__global__ void prep_sort(const int* __restrict__ lengths){
    __shared__ int sl[Bn];
    int tid = threadIdx.x;
    if (tid < Bn) sl[tid] = lengths[tid];
    __syncthreads();
    if (tid < Bn){
        int L = sl[tid]; int r = 0;
#pragma unroll
        for (int k = 0; k < Bn; k++)
            r += (sl[k] > L) || (sl[k] == L && k < tid);
        g_perm[r] = tid;
    }
    if (tid < Tn){
        int c = 0;
#pragma unroll
        for (int k = 0; k < Bn; k++) c += (sl[k] > tid);
        g_na[tid] = c;
    }
}

__global__ void init_state(const float* __restrict__ h0, const float* __restrict__ c0){
    int i = blockIdx.x * blockDim.x + threadIdx.x;
    if (i < Bn * Hn){
        int bp = i >> 10, j = i & (Hn - 1);
        int b = g_perm[bp];
        float h = h0[(size_t)b * Hn + j], c = c0[(size_t)b * Hn + j];
        g_c[0][i]  = c;
        g_ht[0][i] = __float2half_rn(h);
        g_ct[0][i] = __float2half_rn(c);
    }
}

// ---------------------------------------------------------------------------
// fp16 input-projection GEMM (VALIDATED R9/R10) + dead-tile skip
// ---------------------------------------------------------------------------
#define PXB 5120
#define PX_SMEM (2 * PXB)

__global__ void __launch_bounds__(128)
gemm_prex(const float* __restrict__ bias, const int* __restrict__ lengths)
{
    const int nb = blockIdx.y;
    {
        int n0 = nb * 64;
        int b0 = n0 / Tn, t0 = n0 - b0 * Tn;
        bool cross = ((n0 + 63) / Tn) != b0;
        if (!cross && t0 >= __ldg(&lengths[b0])) return;
    }

    extern __shared__ __align__(16) char smc[];
    const uint32_t sb = (uint32_t)__cvta_generic_to_shared(smc);
    const int tid = threadIdx.x;
    const int wid = tid >> 5;
    const int lane = tid & 31;
    const int g = lane >> 2, t = lane & 3;
    const int m = blockIdx.x;

    const uint4* __restrict__ Ap = g_Wpih + (size_t)m * 8192;
    const __half* __restrict__ B = g_X + (size_t)nb * 64 * In;

    float acc[2][8][4];
#pragma unroll
    for (int mt = 0; mt < 2; mt++)
#pragma unroll
        for (int j = 0; j < 8; j++)
#pragma unroll
            for (int q = 0; q < 4; q++) acc[mt][j][q] = 0.f;

#define PX_ST(buf, ck) do {                                                    \
        for (int u = tid; u < 256; u += 128){                                  \
            int rr = u >> 2, uu = u & 3;                                       \
            CPA16(sb + (buf) * PXB + rr * 80 + uu * 16,                        \
                  B + (size_t)rr * In + (ck) * 32 + uu * 8);                   \
        }                                                                      \
    } while (0)

#define PX_LDA(dst, ck) do {                                                   \
        (dst)[0][0] = Ap[((((ck) * 2 + 0) * 4 + wid) * 2 + 0) * 32 + lane];    \
        (dst)[0][1] = Ap[((((ck) * 2 + 0) * 4 + wid) * 2 + 1) * 32 + lane];    \
        (dst)[1][0] = Ap[((((ck) * 2 + 1) * 4 + wid) * 2 + 0) * 32 + lane];    \
        (dst)[1][1] = Ap[((((ck) * 2 + 1) * 4 + wid) * 2 + 1) * 32 + lane];    \
    } while (0)

    PX_ST(0, 0); CPC();
    uint4 av[2][2];
    PX_LDA(av, 0);

#pragma unroll 1
    for (int ch = 0; ch < 16; ch++){
        CPW(0);
        __syncthreads();
        if (ch + 1 < 16){ PX_ST((ch + 1) & 1, ch + 1); CPC(); }
        uint4 nx[2][2];
        if (ch + 1 < 16) PX_LDA(nx, ch + 1);

        const uint32_t Bb = sb + (ch & 1) * PXB;
#pragma unroll
        for (int kk = 0; kk < 2; kk++){
            uint32_t b[8][2];
#pragma unroll
            for (int j = 0; j < 8; j++){
                uint32_t bbase = Bb + (j * 8 + g) * 80 + kk * 32 + t * 4;
                b[j][0] = lds32(bbase);
                b[j][1] = lds32(bbase + 16);
            }
#pragma unroll
            for (int mt = 0; mt < 2; mt++){
                uint4 a = av[kk][mt];
#pragma unroll
                for (int j = 0; j < 8; j++)
                    MMA_F16(acc[mt][j], a.x, a.y, a.z, a.w, b[j][0], b[j][1]);
            }
        }
        if (ch + 1 < 16){
            av[0][0] = nx[0][0]; av[0][1] = nx[0][1];
            av[1][0] = nx[1][0]; av[1][1] = nx[1][1];
        }
    }

#pragma unroll
    for (int mt = 0; mt < 2; mt++){
        int rowb = m * 128 + wid * 32 + mt * 16;
        float bs0 = bias[rowb + g];
        float bs1 = bias[rowb + g + 8];
#pragma unroll
        for (int j = 0; j < 8; j++)
#pragma unroll
            for (int q = 0; q < 4; q++){
                int row = rowb + g + (q >> 1) * 8;
                int n   = blockIdx.y * 64 + j * 8 + t * 2 + (q & 1);
                int bq  = n / Tn, tq = n - bq * Tn;
                g_prex[((size_t)tq * Bn + bq) * G4 + row] =
                    acc[mt][j][q] + ((q >> 1) ? bs1 : bs0);
            }
    }
}

// ---------------------------------------------------------------------------
// Persistent recurrent kernel: single-shot B staging + 8-warp MMA
// ---------------------------------------------------------------------------
#define SWB  98304
#define BBUF 5120
#define PERS_SMEM (SWB + 12 * BBUF)     // 96KB W + 60KB B = 156KB

__device__ __forceinline__ void gridbar(){
    __threadfence();
    __syncthreads();
    if (threadIdx.x == 0){
        unsigned e = *(volatile unsigned*)&g_bar_ep;
        unsigned v = atomicAdd(&g_bar_ct, 1u);
        if (v == NCTA - 1){
            g_bar_ct = 0;
            __threadfence();
            atomicAdd(&g_bar_ep, 1u);
        } else {
            while (*(volatile unsigned*)&g_bar_ep == e) { }
        }
    }
    __syncthreads();
    __threadfence();
}

__global__ void __launch_bounds__(NTHR, 1)
persist_kernel(float* __restrict__ out, int writeC)
{
    extern __shared__ __align__(16) char smc[];
    const uint32_t sb = (uint32_t)__cvta_generic_to_shared(smc);
    const uint4* sW4 = (const uint4*)smc;
    const int tid  = threadIdx.x;
    const int wid  = tid >> 5;
    const int lane = tid & 31;
    const int g = lane >> 2, t = lane & 3;
    const int w4 = wid & 3;          // row-pair within 128-row tile
    const int mt = wid >> 2;         // which m16 of the 32-row pair
    const int cta  = blockIdx.x;
    const int tt   = cta / 3;
    const int sp   = cta % 3;
    const int spk0 = sp * 384;
    const int nch  = (sp == 2) ? 8 : 12;

    // one-time load of packed fp16 W tile
    {
        const uint4* src = &g_Wpk[(size_t)cta * 6144];
        int n4 = nch * 512;
        for (int u = tid; u < n4; u += NTHR)
            CPA16(sb + u * 16, (const char*)(src + u));
        CPC(); CPW(0);
        __syncthreads();
    }

    const size_t BTH = (size_t)Bn * Tn * Hn;

#pragma unroll 1
    for (int tstep = 0; tstep < Tn; tstep++){
        const int par = tstep & 1, np = par ^ 1;
        const int na = __ldg(&g_na[tstep]);
        const int nj = (na + 7) >> 3;
        if (nj == 0) break;
        const int ract = nj << 3;
        const __half* __restrict__ Bsrc = (tt < 32) ? g_ht[par] : g_ct[par];

        // ---- single-shot staging of ALL B chunks ----
        {
            int rr = tid >> 2, uu = tid & 3;
            if (rr < ract){
                const __half* rp = Bsrc + (size_t)rr * Hn + spk0;
                uint32_t dst = sb + SWB + rr * 80 + uu * 16;
#pragma unroll 1
                for (int ck = 0; ck < nch; ck++)
                    CPA16(dst + ck * BBUF, rp + ck * 32 + uu * 8);
            }
            CPC(); CPW(0);
            __syncthreads();
        }

        // ---- MMA: all 8 warps, no internal syncs ----
        float acc[8][4];
#pragma unroll
        for (int j = 0; j < 8; j++)
#pragma unroll
            for (int q = 0; q < 4; q++) acc[j][q] = 0.f;

#pragma unroll 1
        for (int ck = 0; ck < nch; ck++){
            const uint32_t Bb = sb + SWB + ck * BBUF;
#pragma unroll
            for (int kk = 0; kk < 2; kk++){
                uint4 av = sW4[((((ck * 2 + kk) * 4 + w4) * 2 + mt) * 32) + lane];
                uint32_t b[8][2];
#pragma unroll
                for (int j = 0; j < 8; j++) if (j < nj){
                    uint32_t bbase = Bb + (j * 8 + g) * 80 + kk * 32 + t * 4;
                    b[j][0] = lds32(bbase);
                    b[j][1] = lds32(bbase + 16);
                }
#pragma unroll
                for (int j = 0; j < 8; j++) if (j < nj)
                    MMA_F16(acc[j], av.x, av.y, av.z, av.w, b[j][0], b[j][1]);
            }
        }

        // epilogue: partials -> g_P[(sp*64+col)][row], active tiles only
#pragma unroll
        for (int j = 0; j < 8; j++) if (j < nj)
#pragma unroll
            for (int q = 0; q < 4; q++){
                int row = tt * 128 + w4 * 32 + mt * 16 + g + (q >> 1) * 8;
                int col = j * 8 + t * 2 + (q & 1);
                g_P[((size_t)(sp * 64 + col)) * 6144 + row] = acc[j][q];
            }

        gridbar();

        // fused cell phase — active batches only (sorted desc => bp < na)
        const int ncell = na << 10;
        for (int e = cta * NTHR + tid; e < ncell; e += NCTA * NTHR){
            int j  = e & (Hn - 1);
            int bp = e >> 10;
            int borig = __ldg(&g_perm[bp]);

            float si = 0.f, sf = 0.f, sg = 0.f, so = 0.f;
#pragma unroll
            for (int s2 = 0; s2 < 3; s2++){
                const float* Pp = g_P + ((size_t)(s2 * 64 + bp)) * 6144;
                si += Pp[j]        + Pp[4096 + j];
                sf += Pp[1024 + j] + Pp[5120 + j];
                sg += Pp[2048 + j];
                so += Pp[3072 + j];
            }
            size_t pxb = ((size_t)tstep * Bn + borig) * G4 + j;
            float pi = g_prex[pxb]          + si;
            float pf = g_prex[pxb + Hn]     + sf;
            float pg = g_prex[pxb + 2*Hn]   + sg;
            float po = g_prex[pxb + 3*Hn]   + so;
            float cold = g_c[par][e];

            float ig = sigf(pi);
            float fg = sigf(pf);
            float gv = tanhf(pg);
            float cn = fg * cold + ig * gv;
            float og = sigf(po + cn);
            float hn = og * tanhf(cn);

            g_c[np][e]  = cn;
            g_ht[np][e] = __float2half_rn(hn);
            g_ct[np][e] = __float2half_rn(cn);

            size_t ob = ((size_t)borig * Tn + tstep) * Hn + j;
            out[ob] = hn;
            if (writeC) out[BTH + ob] = cn;
        }

        gridbar();
    }
}

// ---------------------------------------------------------------------------
extern "C" void kernel_launch(void* const* d_in, const int* in_sizes, int n_in,
                              void* d_out, int out_size)
{
    const float* x    = (const float*)d_in[0];
    const float* h0   = (const float*)d_in[1];
    const float* c0   = (const float*)d_in[2];
    const float* wih  = (const float*)d_in[3];
    const float* whh  = (const float*)d_in[4];
    const float* wrec = (const float*)d_in[5];
    const float* bias = (const float*)d_in[6];
    const int* lengths = (const int*)d_in[7];
    float* out = (float*)d_out;
    int writeC = (out_size >= 2 * Bn * Tn * Hn) ? 1 : 0;

    cudaFuncSetAttribute(gemm_prex, cudaFuncAttributeMaxDynamicSharedMemorySize, PX_SMEM);
    cudaFuncSetAttribute(persist_kernel, cudaFuncAttributeMaxDynamicSharedMemorySize, PERS_SMEM);

    prep_sort<<<1, 256>>>(lengths);
    pack_w<<<1024, 256>>>(whh, wrec);
    pack_wih<<<512, 256>>>(wih);
    cvt_x<<<1024, 256>>>(x);
    out_zero<<<1024, 256>>>(out, (size_t)out_size / 4);
    init_state<<<256, 256>>>(h0, c0);
    gemm_prex<<<dim3(32, 188), 128, PX_SMEM>>>(bias, lengths);
    persist_kernel<<<NCTA, NTHR, PERS_SMEM>>>(out, writeC);
}